// round 11
// baseline (speedup 1.0000x reference)
#include <cuda_runtime.h>
#include <cuda_bf16.h>
#include <math.h>
#include <stdint.h>

#define Bdim 4
#define Sdim 2048
#define Edim 1024
#define Hdim 16
#define Ddim 64
#define Mrows (Bdim * Sdim)          // 8192
#define HD (Hdim * Ddim)             // 1024
#define GK 1024

// ---------------- scratch (static device globals; no allocs) ----------------
__device__ __nv_bfloat16 g_xn[Mrows * Edim];
__device__ __nv_bfloat16 g_q [Mrows * HD];
__device__ __nv_bfloat16 g_k [Mrows * HD];
__device__ __nv_bfloat16 g_v [Mrows * HD];
__device__ __nv_bfloat16 g_ao[Mrows * HD];
__device__ __nv_bfloat16 g_wt[4 * GK * GK];   // transposed weights [N][K] bf16

// ---------------- helpers ----------------------------------------------------
__device__ __forceinline__ uint32_t packbf(float lo, float hi) {
    uint32_t d;
    asm("cvt.rn.bf16x2.f32 %0, %1, %2;" : "=r"(d) : "f"(hi), "f"(lo));
    return d;
}
__device__ __forceinline__ float ex2f(float x) {
    float y;
    asm("ex2.approx.f32 %0, %1;" : "=f"(y) : "f"(x));
    return y;
}

// D(16x8) += A(16x16,row) * B(16x8,col)  bf16 -> fp32
__device__ __forceinline__ void mma_bf16(float c[4],
                                         uint32_t a0, uint32_t a1, uint32_t a2, uint32_t a3,
                                         uint32_t b0, uint32_t b1) {
    asm volatile(
        "mma.sync.aligned.m16n8k16.row.col.f32.bf16.bf16.f32 "
        "{%0,%1,%2,%3}, {%4,%5,%6,%7}, {%8,%9}, {%0,%1,%2,%3};\n"
        : "+f"(c[0]), "+f"(c[1]), "+f"(c[2]), "+f"(c[3])
        : "r"(a0), "r"(a1), "r"(a2), "r"(a3), "r"(b0), "r"(b1));
}

__device__ __forceinline__ void ldsm4(uint32_t r[4], uint32_t addr) {
    asm volatile("ldmatrix.sync.aligned.m8n8.x4.shared.b16 {%0,%1,%2,%3}, [%4];"
                 : "=r"(r[0]), "=r"(r[1]), "=r"(r[2]), "=r"(r[3])
                 : "r"(addr));
}
__device__ __forceinline__ void ldsm4t(uint32_t r[4], uint32_t addr) {
    asm volatile("ldmatrix.sync.aligned.m8n8.x4.trans.shared.b16 {%0,%1,%2,%3}, [%4];"
                 : "=r"(r[0]), "=r"(r[1]), "=r"(r[2]), "=r"(r[3])
                 : "r"(addr));
}

__device__ __forceinline__ void cp16(uint32_t dst, const void* src) {
    asm volatile("cp.async.cg.shared.global [%0], [%1], 16;" :: "r"(dst), "l"(src));
}
__device__ __forceinline__ void cp_commit() {
    asm volatile("cp.async.commit_group;");
}
template <int N>
__device__ __forceinline__ void cp_wait() {
    asm volatile("cp.async.wait_group %0;" :: "n"(N));
}

// ---------------- LayerNorm (fp32 in -> bf16 out) ----------------------------
__global__ void __launch_bounds__(256) ln_kernel(const float* __restrict__ x,
                                                 const float* __restrict__ gamma,
                                                 const float* __restrict__ beta,
                                                 __nv_bfloat16* __restrict__ y) {
    const int row = blockIdx.x;
    const int tid = threadIdx.x;
    const float4 xv = reinterpret_cast<const float4*>(x + (size_t)row * Edim)[tid];
    float s  = xv.x + xv.y + xv.z + xv.w;
    float ss = xv.x * xv.x + xv.y * xv.y + xv.z * xv.z + xv.w * xv.w;
    #pragma unroll
    for (int m = 16; m; m >>= 1) {
        s  += __shfl_xor_sync(0xffffffffu, s,  m);
        ss += __shfl_xor_sync(0xffffffffu, ss, m);
    }
    __shared__ float sh_s[8], sh_ss[8];
    __shared__ float s_mu, s_rstd;
    const int w = tid >> 5, l = tid & 31;
    if (l == 0) { sh_s[w] = s; sh_ss[w] = ss; }
    __syncthreads();
    if (w == 0) {
        float a = (l < 8) ? sh_s[l]  : 0.f;
        float c = (l < 8) ? sh_ss[l] : 0.f;
        #pragma unroll
        for (int m = 4; m; m >>= 1) {
            a += __shfl_xor_sync(0xffffffffu, a, m);
            c += __shfl_xor_sync(0xffffffffu, c, m);
        }
        if (l == 0) {
            float mu  = a * (1.0f / Edim);
            float var = c * (1.0f / Edim) - mu * mu;
            s_mu = mu;
            s_rstd = rsqrtf(var + 1e-5f);
        }
    }
    __syncthreads();
    const float mu = s_mu, rstd = s_rstd;
    const float4 gv = reinterpret_cast<const float4*>(gamma)[tid];
    const float4 bv = reinterpret_cast<const float4*>(beta)[tid];
    uint2 o2;
    o2.x = packbf((xv.x - mu) * rstd * gv.x + bv.x, (xv.y - mu) * rstd * gv.y + bv.y);
    o2.y = packbf((xv.z - mu) * rstd * gv.z + bv.z, (xv.w - mu) * rstd * gv.w + bv.w);
    *reinterpret_cast<uint2*>(y + (size_t)row * Edim + tid * 4) = o2;
}

// ---------------- weight transpose: W[K,N] fp32 -> WT[N,K] bf16 --------------
__global__ void __launch_bounds__(256) transpose_kernel(const float* __restrict__ Wq,
                                                        const float* __restrict__ Wk,
                                                        const float* __restrict__ Wv,
                                                        const float* __restrict__ Wo,
                                                        __nv_bfloat16* __restrict__ wt) {
    __shared__ float t[32][33];
    const int z = blockIdx.z;
    const float* W = (z == 0) ? Wq : (z == 1) ? Wk : (z == 2) ? Wv : Wo;
    __nv_bfloat16* T = wt + (size_t)z * GK * GK;
    const int x0 = blockIdx.x * 32, y0 = blockIdx.y * 32;
    const int tx = threadIdx.x & 31, ty = threadIdx.x >> 5;   // 32x8
    #pragma unroll
    for (int i = 0; i < 32; i += 8)
        t[ty + i][tx] = W[(size_t)(y0 + ty + i) * GK + x0 + tx];
    __syncthreads();
    #pragma unroll
    for (int i = 0; i < 32; i += 8)
        T[(size_t)(x0 + ty + i) * GK + y0 + tx] = __float2bfloat16(t[tx][ty + i]);
}

// ---------------- bf16 GEMM: 128x256 CTA tile, 64x64 warp tile, BK=32 -------
#define BK 32
#define ROWB 80u
#define STG_A 0u
#define STG_B 10240u                       // A: 128 rows * 80B
#define STAGE_BYTES 30720u                 // + B: 256 rows * 80B
#define GSTAGES 3
#define GEMM_SMEM_BYTES (GSTAGES * STAGE_BYTES)   // 92160

template <bool BF16OUT>
__device__ __forceinline__ void gemm_body(const __nv_bfloat16* __restrict__ A,
                                          const __nv_bfloat16* __restrict__ WT,
                                          const float* __restrict__ bias,
                                          const float* __restrict__ res,
                                          void* __restrict__ C,
                                          int bx, int by, float oscale) {
    extern __shared__ __align__(16) char smem[];
    const uint32_t s0 = (uint32_t)__cvta_generic_to_shared(smem);

    const int tid  = threadIdx.x;
    const int lane = tid & 31;
    const int wid  = tid >> 5;
    const int g  = lane >> 2;
    const int tg = lane & 3;
    const int wm = wid >> 2;      // 0..1 -> 64 rows
    const int wn = wid & 3;       // 0..3 -> 64 cols
    const int row0 = by * 128;
    const int col0 = bx * 256;
    const int N = 1024;

    // LDSM lane bases (byte offsets within a stage) — mapping identical to the
    // proven 64x32 version, only the wn multiplier scaled (32 -> 64).
    const uint32_t a_off = STG_A + (uint32_t)(wm * 64 + (lane & 15)) * ROWB
                                 + (uint32_t)((lane >> 4) << 4);
    const uint32_t b_off = STG_B + (uint32_t)(wn * 64 + (lane & 7) + ((lane >> 4) << 3)) * ROWB
                                 + (uint32_t)(((lane >> 3) & 1) << 4);

    auto issue_tile = [&](int t) {
        const uint32_t sb = s0 + (uint32_t)(t % GSTAGES) * STAGE_BYTES;
        const int gk = t * BK;
        #pragma unroll
        for (int i = 0; i < 6; i++) {
            const int idx = tid + i * 256;       // 0..1535
            const int j = idx & 3;
            if (idx < 512) {
                const int r = idx >> 2;
                cp16(sb + STG_A + r * ROWB + j * 16u,
                     A + (size_t)(row0 + r) * GK + gk + j * 8);
            } else {
                const int r = (idx - 512) >> 2;  // 0..255
                cp16(sb + STG_B + r * ROWB + j * 16u,
                     WT + (size_t)(col0 + r) * GK + gk + j * 8);
            }
        }
        cp_commit();
    };

    issue_tile(0);
    issue_tile(1);

    float acc[4][8][4] = {};
    const int NIT = GK / BK;     // 32

    for (int it = 0; it < NIT; it++) {
        cp_wait<GSTAGES - 2>();
        __syncthreads();

        if (it + GSTAGES - 1 < NIT) issue_tile(it + GSTAGES - 1);
        else cp_commit();

        const uint32_t sb = s0 + (uint32_t)(it % GSTAGES) * STAGE_BYTES;
        #pragma unroll
        for (int kb = 0; kb < 2; kb++) {
            uint32_t af[4][4], bf[4][4];
            #pragma unroll
            for (int mi = 0; mi < 4; mi++)
                ldsm4(af[mi], sb + a_off + (uint32_t)(mi * 16) * ROWB + kb * 32u);
            #pragma unroll
            for (int nb = 0; nb < 4; nb++)
                ldsm4(bf[nb], sb + b_off + (uint32_t)(nb * 16) * ROWB + kb * 32u);
            #pragma unroll
            for (int mi = 0; mi < 4; mi++)
                #pragma unroll
                for (int nb = 0; nb < 4; nb++) {
                    mma_bf16(acc[mi][nb * 2],     af[mi][0], af[mi][1], af[mi][2], af[mi][3],
                             bf[nb][0], bf[nb][1]);
                    mma_bf16(acc[mi][nb * 2 + 1], af[mi][0], af[mi][1], af[mi][2], af[mi][3],
                             bf[nb][2], bf[nb][3]);
                }
        }
        __syncthreads();
    }

    #pragma unroll
    for (int mi = 0; mi < 4; mi++) {
        const int r1 = row0 + wm * 64 + mi * 16 + g;
        const int r2 = r1 + 8;
        #pragma unroll
        for (int ni = 0; ni < 8; ni++) {
            const int cb = col0 + wn * 64 + ni * 8 + 2 * tg;
            float v0 = (acc[mi][ni][0] + bias[cb])     * oscale;
            float v1 = (acc[mi][ni][1] + bias[cb + 1]) * oscale;
            float v2 = (acc[mi][ni][2] + bias[cb])     * oscale;
            float v3 = (acc[mi][ni][3] + bias[cb + 1]) * oscale;
            if (BF16OUT) {
                ((uint32_t*)C)[(size_t)r1 * (N / 2) + (cb >> 1)] = packbf(v0, v1);
                ((uint32_t*)C)[(size_t)r2 * (N / 2) + (cb >> 1)] = packbf(v2, v3);
            } else {
                const float2 r1v = *reinterpret_cast<const float2*>(res + (size_t)r1 * N + cb);
                const float2 r2v = *reinterpret_cast<const float2*>(res + (size_t)r2 * N + cb);
                float2 w1; w1.x = v0 + r1v.x; w1.y = v1 + r1v.y;
                float2 w2; w2.x = v2 + r2v.x; w2.y = v3 + r2v.y;
                *reinterpret_cast<float2*>((float*)C + (size_t)r1 * N + cb) = w1;
                *reinterpret_cast<float2*>((float*)C + (size_t)r2 * N + cb) = w2;
            }
        }
    }
}

// fused QKV: grid (12, 64); blockIdx.x: matrix (x>>2), col tile (x&3)
__global__ void __launch_bounds__(256) qkv_gemm_kernel(const __nv_bfloat16* __restrict__ A,
                                                       const __nv_bfloat16* __restrict__ wt,
                                                       const float* __restrict__ bq,
                                                       const float* __restrict__ bk,
                                                       const float* __restrict__ bv,
                                                       __nv_bfloat16* __restrict__ Cq,
                                                       __nv_bfloat16* __restrict__ Ck,
                                                       __nv_bfloat16* __restrict__ Cv) {
    const int mat = blockIdx.x >> 2;
    const int bx  = blockIdx.x & 3;
    const __nv_bfloat16* WT = wt + (size_t)mat * GK * GK;
    const float* bias = (mat == 0) ? bq : (mat == 1) ? bk : bv;
    __nv_bfloat16* C  = (mat == 0) ? Cq : (mat == 1) ? Ck : Cv;
    const float sc = (mat == 0) ? 0.1803368801111354f : 1.0f;   // 0.125 * log2(e)
    gemm_body<true>(A, WT, bias, nullptr, C, bx, blockIdx.y, sc);
}

__global__ void __launch_bounds__(256) o_gemm_kernel(const __nv_bfloat16* __restrict__ A,
                                                     const __nv_bfloat16* __restrict__ wt,
                                                     const float* __restrict__ bo,
                                                     const float* __restrict__ res,
                                                     float* __restrict__ out) {
    gemm_body<false>(A, wt + (size_t)3 * GK * GK, bo, res, out, blockIdx.x, blockIdx.y, 1.0f);
}

// ---------------- Flash attention (causal), bf16, in-register P -------------
// grid (S/128, H, B), 256 threads (8 warps). Warp w owns 16 query rows.
// Scores in log2 domain (Q pre-scaled); softmax uses ex2.
// smem: Q tile + 3-deep KV ring => ONE __syncthreads per tile.
#define TROW 144u
#define QTILE_B (128u * TROW)            // 18432
#define KVTILE_B (64u * TROW)            // 9216
#define KVBUF (2u * KVTILE_B)            // K+V per buffer: 18432
#define ATTN_SMEM_BYTES (QTILE_B + 3 * KVBUF)   // 73728

__global__ void __launch_bounds__(256, 2) attn_bf16_kernel(const __nv_bfloat16* __restrict__ Q,
                                                           const __nv_bfloat16* __restrict__ K,
                                                           const __nv_bfloat16* __restrict__ V,
                                                           __nv_bfloat16* __restrict__ O) {
    extern __shared__ __align__(16) char sm[];
    const uint32_t q_u32  = (uint32_t)__cvta_generic_to_shared(sm);
    const uint32_t kv_u32 = q_u32 + QTILE_B;

    const int tid  = threadIdx.x;
    const int lane = tid & 31;
    const int wid  = tid >> 5;           // 0..7
    const int g  = lane >> 2;
    const int tg = lane & 3;
    const int rbase = wid * 16;          // warp owns rows rbase..rbase+15
    const int qblk = (int)gridDim.x - 1 - (int)blockIdx.x;   // LPT: heavy CTAs first
    const int q0 = qblk * 128;
    const int h = blockIdx.y, b = blockIdx.z;
    const size_t base = (size_t)b * Sdim * HD + (size_t)h * Ddim;

    // LDSM lane bases
    const uint32_t q_loff = (uint32_t)(rbase + (lane & 15)) * TROW + (uint32_t)((lane >> 4) << 4);
    const uint32_t b_loff = (uint32_t)((lane & 7) + ((lane >> 4) << 3)) * TROW
                          + (uint32_t)(((lane >> 3) & 1) << 4);
    const uint32_t v_loff = (uint32_t)((lane & 7) + (((lane >> 3) & 1) << 3)) * TROW
                          + (uint32_t)((lane >> 4) << 4);

    const int ntiles = (q0 >> 6) + 2;

    auto issue_kv = [&](int t) {
        const uint32_t kvb = kv_u32 + (uint32_t)(t % 3) * KVBUF;
        const int jr = t * 64;
        #pragma unroll
        for (int i = 0; i < 4; i++) {
            const int idx = tid + i * 256;
            const int j = idx & 7;
            if (idx < 512) {
                const int r = idx >> 3;
                cp16(kvb + r * TROW + j * 16u, K + base + (size_t)(jr + r) * HD + j * 8);
            } else {
                const int r = (idx - 512) >> 3;
                cp16(kvb + KVTILE_B + r * TROW + j * 16u,
                     V + base + (size_t)(jr + r) * HD + j * 8);
            }
        }
    };

    // prologue: G0 = Q(128 rows) + KV tile 0 ; G1 = KV tile 1 (always exists)
    #pragma unroll
    for (int i = 0; i < 4; i++) {
        const int idx = tid + i * 256;
        const int r = idx >> 3, j = idx & 7;
        cp16(q_u32 + r * TROW + j * 16u, Q + base + (size_t)(q0 + r) * HD + j * 8);
    }
    issue_kv(0);
    cp_commit();
    issue_kv(1);
    cp_commit();

    float m1 = -1e30f, m2 = -1e30f, l1 = 0.f, l2 = 0.f;
    float o[8][4] = {};
    const int grow_base = q0 + rbase;    // warp's first global query row
    const int grow1 = grow_base + g, grow2 = grow1 + 8;

    for (int jt = 0; jt < ntiles; jt++) {
        cp_wait<1>();
        __syncthreads();     // tile jt ready; all warps done with tile jt-1's buffer

        if (jt + 2 < ntiles) issue_kv(jt + 2);
        cp_commit();

        const int j0 = jt * 64;
        const uint32_t kb32 = kv_u32 + (uint32_t)(jt % 3) * KVBUF;
        const uint32_t vb32 = kb32 + KVTILE_B;
        const bool active = (j0 <= grow_base + 15);   // warp-uniform

        if (active) {
            // S = Q K^T (16 rows x 64 cols), log2 domain
            float s[8][4] = {};
            #pragma unroll
            for (int kb = 0; kb < 4; kb++) {
                uint32_t af[4];
                ldsm4(af, q_u32 + q_loff + kb * 32u);
                #pragma unroll
                for (int nb = 0; nb < 4; nb++) {
                    uint32_t bf[4];
                    ldsm4(bf, kb32 + b_loff + (uint32_t)(nb * 16) * TROW + kb * 32u);
                    mma_bf16(s[nb * 2],     af[0], af[1], af[2], af[3], bf[0], bf[1]);
                    mma_bf16(s[nb * 2 + 1], af[0], af[1], af[2], af[3], bf[2], bf[3]);
                }
            }

            // online softmax (base-2); p stored back into s
            const bool diag = (j0 + 63 > grow_base);
            float rm1 = -1e30f, rm2 = -1e30f;
            #pragma unroll
            for (int nt = 0; nt < 8; nt++) {
                if (diag) {
                    const int c0 = j0 + nt * 8 + 2 * tg;
                    if (c0     > grow1) s[nt][0] = -1e30f;
                    if (c0 + 1 > grow1) s[nt][1] = -1e30f;
                    if (c0     > grow2) s[nt][2] = -1e30f;
                    if (c0 + 1 > grow2) s[nt][3] = -1e30f;
                }
                rm1 = fmaxf(rm1, fmaxf(s[nt][0], s[nt][1]));
                rm2 = fmaxf(rm2, fmaxf(s[nt][2], s[nt][3]));
            }
            rm1 = fmaxf(rm1, __shfl_xor_sync(0xffffffffu, rm1, 1));
            rm1 = fmaxf(rm1, __shfl_xor_sync(0xffffffffu, rm1, 2));
            rm2 = fmaxf(rm2, __shfl_xor_sync(0xffffffffu, rm2, 1));
            rm2 = fmaxf(rm2, __shfl_xor_sync(0xffffffffu, rm2, 2));

            const float mn1 = fmaxf(m1, rm1), mn2 = fmaxf(m2, rm2);
            const float sc1 = ex2f(m1 - mn1), sc2 = ex2f(m2 - mn2);
            m1 = mn1; m2 = mn2;

            float sum1 = 0.f, sum2 = 0.f;
            #pragma unroll
            for (int nt = 0; nt < 8; nt++) {
                s[nt][0] = ex2f(s[nt][0] - mn1);
                s[nt][1] = ex2f(s[nt][1] - mn1);
                s[nt][2] = ex2f(s[nt][2] - mn2);
                s[nt][3] = ex2f(s[nt][3] - mn2);
                sum1 += s[nt][0] + s[nt][1];
                sum2 += s[nt][2] + s[nt][3];
            }
            sum1 += __shfl_xor_sync(0xffffffffu, sum1, 1);
            sum1 += __shfl_xor_sync(0xffffffffu, sum1, 2);
            sum2 += __shfl_xor_sync(0xffffffffu, sum2, 1);
            sum2 += __shfl_xor_sync(0xffffffffu, sum2, 2);
            l1 = l1 * sc1 + sum1;
            l2 = l2 * sc2 + sum2;

            #pragma unroll
            for (int nt = 0; nt < 8; nt++) {
                o[nt][0] *= sc1; o[nt][1] *= sc1;
                o[nt][2] *= sc2; o[nt][3] *= sc2;
            }

            // O += P V : P A-fragments built directly from S C-fragments
            #pragma unroll
            for (int kb = 0; kb < 4; kb++) {
                uint32_t pa[4];
                pa[0] = packbf(s[2 * kb][0],     s[2 * kb][1]);
                pa[1] = packbf(s[2 * kb][2],     s[2 * kb][3]);
                pa[2] = packbf(s[2 * kb + 1][0], s[2 * kb + 1][1]);
                pa[3] = packbf(s[2 * kb + 1][2], s[2 * kb + 1][3]);
                #pragma unroll
                for (int nb = 0; nb < 4; nb++) {
                    uint32_t bf[4];
                    ldsm4t(bf, vb32 + v_loff + (uint32_t)(kb * 16) * TROW + nb * 32u);
                    mma_bf16(o[nb * 2],     pa[0], pa[1], pa[2], pa[3], bf[0], bf[1]);
                    mma_bf16(o[nb * 2 + 1], pa[0], pa[1], pa[2], pa[3], bf[2], bf[3]);
                }
            }
        }
    }

    const float inv1 = 1.0f / l1;
    const float inv2 = 1.0f / l2;
    #pragma unroll
    for (int nt = 0; nt < 8; nt++) {
        const int cb = nt * 8 + 2 * tg;
        *reinterpret_cast<uint32_t*>(O + base + (size_t)grow1 * HD + cb) =
            packbf(o[nt][0] * inv1, o[nt][1] * inv1);
        *reinterpret_cast<uint32_t*>(O + base + (size_t)grow2 * HD + cb) =
            packbf(o[nt][2] * inv2, o[nt][3] * inv2);
    }
}

// ---------------- launch ----------------------------------------------------
extern "C" void kernel_launch(void* const* d_in, const int* in_sizes, int n_in,
                              void* d_out, int out_size) {
    const float* x     = (const float*)d_in[0];
    const float* gamma = (const float*)d_in[1];
    const float* beta  = (const float*)d_in[2];
    const float* Wq    = (const float*)d_in[3];
    const float* bq    = (const float*)d_in[4];
    const float* Wk    = (const float*)d_in[5];
    const float* bk    = (const float*)d_in[6];
    const float* Wv    = (const float*)d_in[7];
    const float* bv    = (const float*)d_in[8];
    const float* Wo    = (const float*)d_in[9];
    const float* bo    = (const float*)d_in[10];
    float* out = (float*)d_out;

    __nv_bfloat16 *xn, *qp, *kp, *vp, *ao, *wt;
    cudaGetSymbolAddress((void**)&xn, g_xn);
    cudaGetSymbolAddress((void**)&qp, g_q);
    cudaGetSymbolAddress((void**)&kp, g_k);
    cudaGetSymbolAddress((void**)&vp, g_v);
    cudaGetSymbolAddress((void**)&ao, g_ao);
    cudaGetSymbolAddress((void**)&wt, g_wt);

    ln_kernel<<<Mrows, 256>>>(x, gamma, beta, xn);
    transpose_kernel<<<dim3(32, 32, 4), 256>>>(Wq, Wk, Wv, Wo, wt);

    cudaFuncSetAttribute(qkv_gemm_kernel, cudaFuncAttributeMaxDynamicSharedMemorySize,
                         GEMM_SMEM_BYTES);
    cudaFuncSetAttribute(o_gemm_kernel, cudaFuncAttributeMaxDynamicSharedMemorySize,
                         GEMM_SMEM_BYTES);

    qkv_gemm_kernel<<<dim3(12, Mrows / 128), 256, GEMM_SMEM_BYTES>>>(
        xn, wt, bq, bk, bv, qp, kp, vp);

    cudaFuncSetAttribute(attn_bf16_kernel, cudaFuncAttributeMaxDynamicSharedMemorySize,
                         ATTN_SMEM_BYTES);
    attn_bf16_kernel<<<dim3(Sdim / 128, Hdim, Bdim), 256, ATTN_SMEM_BYTES>>>(qp, kp, vp, ao);

    o_gemm_kernel<<<dim3(4, Mrows / 128), 256, GEMM_SMEM_BYTES>>>(ao, wt, bo, x, out);
}

// round 12
// speedup vs baseline: 1.0975x; 1.0975x over previous
#include <cuda_runtime.h>
#include <cuda_bf16.h>
#include <math.h>
#include <stdint.h>

#define Bdim 4
#define Sdim 2048
#define Edim 1024
#define Hdim 16
#define Ddim 64
#define Mrows (Bdim * Sdim)          // 8192
#define HD (Hdim * Ddim)             // 1024
#define GK 1024

// ---------------- scratch (static device globals; no allocs) ----------------
__device__ __nv_bfloat16 g_xn[Mrows * Edim];
__device__ __nv_bfloat16 g_q [Mrows * HD];
__device__ __nv_bfloat16 g_k [Mrows * HD];
__device__ __nv_bfloat16 g_v [Mrows * HD];
__device__ __nv_bfloat16 g_ao[Mrows * HD];
__device__ __nv_bfloat16 g_wt[4 * GK * GK];   // transposed weights [N][K] bf16

// ---------------- helpers ----------------------------------------------------
__device__ __forceinline__ uint32_t packbf(float lo, float hi) {
    uint32_t d;
    asm("cvt.rn.bf16x2.f32 %0, %1, %2;" : "=r"(d) : "f"(hi), "f"(lo));
    return d;
}
__device__ __forceinline__ float ex2f(float x) {
    float y;
    asm("ex2.approx.f32 %0, %1;" : "=f"(y) : "f"(x));
    return y;
}

// D(16x8) += A(16x16,row) * B(16x8,col)  bf16 -> fp32
__device__ __forceinline__ void mma_bf16(float c[4],
                                         uint32_t a0, uint32_t a1, uint32_t a2, uint32_t a3,
                                         uint32_t b0, uint32_t b1) {
    asm volatile(
        "mma.sync.aligned.m16n8k16.row.col.f32.bf16.bf16.f32 "
        "{%0,%1,%2,%3}, {%4,%5,%6,%7}, {%8,%9}, {%0,%1,%2,%3};\n"
        : "+f"(c[0]), "+f"(c[1]), "+f"(c[2]), "+f"(c[3])
        : "r"(a0), "r"(a1), "r"(a2), "r"(a3), "r"(b0), "r"(b1));
}

__device__ __forceinline__ void ldsm4(uint32_t r[4], uint32_t addr) {
    asm volatile("ldmatrix.sync.aligned.m8n8.x4.shared.b16 {%0,%1,%2,%3}, [%4];"
                 : "=r"(r[0]), "=r"(r[1]), "=r"(r[2]), "=r"(r[3])
                 : "r"(addr));
}
__device__ __forceinline__ void ldsm4t(uint32_t r[4], uint32_t addr) {
    asm volatile("ldmatrix.sync.aligned.m8n8.x4.trans.shared.b16 {%0,%1,%2,%3}, [%4];"
                 : "=r"(r[0]), "=r"(r[1]), "=r"(r[2]), "=r"(r[3])
                 : "r"(addr));
}

__device__ __forceinline__ void cp16(uint32_t dst, const void* src) {
    asm volatile("cp.async.cg.shared.global [%0], [%1], 16;" :: "r"(dst), "l"(src));
}
__device__ __forceinline__ void cp_commit() {
    asm volatile("cp.async.commit_group;");
}
template <int N>
__device__ __forceinline__ void cp_wait() {
    asm volatile("cp.async.wait_group %0;" :: "n"(N));
}

// ---------------- merged prep: LayerNorm (blocks 0..8191) + transpose -------
// LN: fp32 x -> bf16 xn. Transpose: W[K,N] fp32 -> WT[N,K] bf16.
__global__ void __launch_bounds__(256) prep_kernel(const float* __restrict__ x,
                                                   const float* __restrict__ gamma,
                                                   const float* __restrict__ beta,
                                                   __nv_bfloat16* __restrict__ y,
                                                   const float* __restrict__ Wq,
                                                   const float* __restrict__ Wk,
                                                   const float* __restrict__ Wv,
                                                   const float* __restrict__ Wo,
                                                   __nv_bfloat16* __restrict__ wt) {
    __shared__ float tsh[32][33];
    const int tid = threadIdx.x;

    if (blockIdx.x < Mrows) {
        // ---------------- LayerNorm ----------------
        const int row = blockIdx.x;
        const float4 xv = reinterpret_cast<const float4*>(x + (size_t)row * Edim)[tid];
        float s  = xv.x + xv.y + xv.z + xv.w;
        float ss = xv.x * xv.x + xv.y * xv.y + xv.z * xv.z + xv.w * xv.w;
        #pragma unroll
        for (int m = 16; m; m >>= 1) {
            s  += __shfl_xor_sync(0xffffffffu, s,  m);
            ss += __shfl_xor_sync(0xffffffffu, ss, m);
        }
        __shared__ float sh_s[8], sh_ss[8];
        __shared__ float s_mu, s_rstd;
        const int w = tid >> 5, l = tid & 31;
        if (l == 0) { sh_s[w] = s; sh_ss[w] = ss; }
        __syncthreads();
        if (w == 0) {
            float a = (l < 8) ? sh_s[l]  : 0.f;
            float c = (l < 8) ? sh_ss[l] : 0.f;
            #pragma unroll
            for (int m = 4; m; m >>= 1) {
                a += __shfl_xor_sync(0xffffffffu, a, m);
                c += __shfl_xor_sync(0xffffffffu, c, m);
            }
            if (l == 0) {
                float mu  = a * (1.0f / Edim);
                float var = c * (1.0f / Edim) - mu * mu;
                s_mu = mu;
                s_rstd = rsqrtf(var + 1e-5f);
            }
        }
        __syncthreads();
        const float mu = s_mu, rstd = s_rstd;
        const float4 gv = reinterpret_cast<const float4*>(gamma)[tid];
        const float4 bv = reinterpret_cast<const float4*>(beta)[tid];
        uint2 o2;
        o2.x = packbf((xv.x - mu) * rstd * gv.x + bv.x, (xv.y - mu) * rstd * gv.y + bv.y);
        o2.y = packbf((xv.z - mu) * rstd * gv.z + bv.z, (xv.w - mu) * rstd * gv.w + bv.w);
        *reinterpret_cast<uint2*>(y + (size_t)row * Edim + tid * 4) = o2;
    } else {
        // ---------------- weight transpose ----------------
        const int bid = blockIdx.x - Mrows;
        const int z = bid >> 10;
        const int rem = bid & 1023;
        const int x0 = (rem & 31) << 5, y0 = (rem >> 5) << 5;
        const float* W = (z == 0) ? Wq : (z == 1) ? Wk : (z == 2) ? Wv : Wo;
        __nv_bfloat16* T = wt + (size_t)z * GK * GK;
        const int tx = tid & 31, ty = tid >> 5;   // 32x8
        #pragma unroll
        for (int i = 0; i < 32; i += 8)
            tsh[ty + i][tx] = W[(size_t)(y0 + ty + i) * GK + x0 + tx];
        __syncthreads();
        #pragma unroll
        for (int i = 0; i < 32; i += 8)
            T[(size_t)(x0 + ty + i) * GK + y0 + tx] = __float2bfloat16(tsh[tx][ty + i]);
    }
}

// ---------------- bf16 GEMM: 128x128 tile, BK=32, 5-stage cp.async ----------
#define BK 32
#define ROWB 80u
#define STG_A 0u
#define STG_B 10240u
#define STAGE_BYTES 20480u
#define GSTAGES 5
#define GEMM_SMEM_BYTES (GSTAGES * STAGE_BYTES)   // 102400

template <bool BF16OUT>
__device__ __forceinline__ void gemm_body(const __nv_bfloat16* __restrict__ A,
                                          const __nv_bfloat16* __restrict__ WT,
                                          const float* __restrict__ bias,
                                          const float* __restrict__ res,
                                          void* __restrict__ C,
                                          int bx, int by, float oscale) {
    extern __shared__ __align__(16) char smem[];
    const uint32_t s0 = (uint32_t)__cvta_generic_to_shared(smem);

    const int tid  = threadIdx.x;
    const int lane = tid & 31;
    const int wid  = tid >> 5;
    const int g  = lane >> 2;
    const int tg = lane & 3;
    const int wm = wid >> 2;
    const int wn = wid & 3;
    const int row0 = by * 128;
    const int col0 = bx * 128;
    const int N = 1024;

    const uint32_t a_off = STG_A + (uint32_t)(wm * 64 + (lane & 15)) * ROWB
                                 + (uint32_t)((lane >> 4) << 4);
    const uint32_t b_off = STG_B + (uint32_t)(wn * 32 + (lane & 7) + ((lane >> 4) << 3)) * ROWB
                                 + (uint32_t)(((lane >> 3) & 1) << 4);

    auto issue_tile = [&](int t) {
        const uint32_t sb = s0 + (uint32_t)(t % GSTAGES) * STAGE_BYTES;
        const int gk = t * BK;
        #pragma unroll
        for (int i = 0; i < 4; i++) {
            const int idx = tid + i * 256;
            const int r = (idx & 511) >> 2;
            const int j = idx & 3;
            if (idx < 512)
                cp16(sb + STG_A + r * ROWB + j * 16u,
                     A + (size_t)(row0 + r) * GK + gk + j * 8);
            else
                cp16(sb + STG_B + r * ROWB + j * 16u,
                     WT + (size_t)(col0 + r) * GK + gk + j * 8);
        }
        cp_commit();
    };

    issue_tile(0);
    issue_tile(1);
    issue_tile(2);
    issue_tile(3);

    float acc[4][4][4] = {};
    const int NIT = GK / BK;     // 32

    for (int it = 0; it < NIT; it++) {
        cp_wait<GSTAGES - 2>();
        __syncthreads();

        if (it + GSTAGES - 1 < NIT) issue_tile(it + GSTAGES - 1);
        else cp_commit();

        const uint32_t sb = s0 + (uint32_t)(it % GSTAGES) * STAGE_BYTES;
        #pragma unroll
        for (int kb = 0; kb < 2; kb++) {
            uint32_t af[4][4], bf[2][4];
            #pragma unroll
            for (int mi = 0; mi < 4; mi++)
                ldsm4(af[mi], sb + a_off + (uint32_t)(mi * 16) * ROWB + kb * 32u);
            #pragma unroll
            for (int nb = 0; nb < 2; nb++)
                ldsm4(bf[nb], sb + b_off + (uint32_t)(nb * 16) * ROWB + kb * 32u);
            #pragma unroll
            for (int mi = 0; mi < 4; mi++)
                #pragma unroll
                for (int nb = 0; nb < 2; nb++) {
                    mma_bf16(acc[mi][nb * 2],     af[mi][0], af[mi][1], af[mi][2], af[mi][3],
                             bf[nb][0], bf[nb][1]);
                    mma_bf16(acc[mi][nb * 2 + 1], af[mi][0], af[mi][1], af[mi][2], af[mi][3],
                             bf[nb][2], bf[nb][3]);
                }
        }
        __syncthreads();
    }

    #pragma unroll
    for (int mi = 0; mi < 4; mi++) {
        const int r1 = row0 + wm * 64 + mi * 16 + g;
        const int r2 = r1 + 8;
        #pragma unroll
        for (int ni = 0; ni < 4; ni++) {
            const int cb = col0 + wn * 32 + ni * 8 + 2 * tg;
            float v0 = (acc[mi][ni][0] + bias[cb])     * oscale;
            float v1 = (acc[mi][ni][1] + bias[cb + 1]) * oscale;
            float v2 = (acc[mi][ni][2] + bias[cb])     * oscale;
            float v3 = (acc[mi][ni][3] + bias[cb + 1]) * oscale;
            if (BF16OUT) {
                ((uint32_t*)C)[(size_t)r1 * (N / 2) + (cb >> 1)] = packbf(v0, v1);
                ((uint32_t*)C)[(size_t)r2 * (N / 2) + (cb >> 1)] = packbf(v2, v3);
            } else {
                const float2 r1v = *reinterpret_cast<const float2*>(res + (size_t)r1 * N + cb);
                const float2 r2v = *reinterpret_cast<const float2*>(res + (size_t)r2 * N + cb);
                float2 w1; w1.x = v0 + r1v.x; w1.y = v1 + r1v.y;
                float2 w2; w2.x = v2 + r2v.x; w2.y = v3 + r2v.y;
                *reinterpret_cast<float2*>((float*)C + (size_t)r1 * N + cb) = w1;
                *reinterpret_cast<float2*>((float*)C + (size_t)r2 * N + cb) = w2;
            }
        }
    }
}

// fused QKV: grid (24, 64); Q output pre-scaled by log2(e)/sqrt(D)
__global__ void __launch_bounds__(256, 2) qkv_gemm_kernel(const __nv_bfloat16* __restrict__ A,
                                                          const __nv_bfloat16* __restrict__ wt,
                                                          const float* __restrict__ bq,
                                                          const float* __restrict__ bk,
                                                          const float* __restrict__ bv,
                                                          __nv_bfloat16* __restrict__ Cq,
                                                          __nv_bfloat16* __restrict__ Ck,
                                                          __nv_bfloat16* __restrict__ Cv) {
    const int mat = blockIdx.x >> 3;
    const int bx  = blockIdx.x & 7;
    const __nv_bfloat16* WT = wt + (size_t)mat * GK * GK;
    const float* bias = (mat == 0) ? bq : (mat == 1) ? bk : bv;
    __nv_bfloat16* C  = (mat == 0) ? Cq : (mat == 1) ? Ck : Cv;
    const float sc = (mat == 0) ? 0.1803368801111354f : 1.0f;   // 0.125 * log2(e)
    gemm_body<true>(A, WT, bias, nullptr, C, bx, blockIdx.y, sc);
}

__global__ void __launch_bounds__(256, 2) o_gemm_kernel(const __nv_bfloat16* __restrict__ A,
                                                        const __nv_bfloat16* __restrict__ wt,
                                                        const float* __restrict__ bo,
                                                        const float* __restrict__ res,
                                                        float* __restrict__ out) {
    gemm_body<false>(A, wt + (size_t)3 * GK * GK, bo, res, out, blockIdx.x, blockIdx.y, 1.0f);
}

// ---------------- Flash attention (causal), bf16, in-register P -------------
// grid (S/128, H, B), 256 threads (8 warps). Warp w owns 16 query rows.
// Scores in log2 domain (Q pre-scaled); softmax uses ex2.
// smem: Q tile + 3-deep KV ring => ONE __syncthreads per tile.
#define TROW 144u
#define QTILE_B (128u * TROW)            // 18432
#define KVTILE_B (64u * TROW)            // 9216
#define KVBUF (2u * KVTILE_B)            // K+V per buffer: 18432
#define ATTN_SMEM_BYTES (QTILE_B + 3 * KVBUF)   // 73728

__global__ void __launch_bounds__(256, 2) attn_bf16_kernel(const __nv_bfloat16* __restrict__ Q,
                                                           const __nv_bfloat16* __restrict__ K,
                                                           const __nv_bfloat16* __restrict__ V,
                                                           __nv_bfloat16* __restrict__ O) {
    extern __shared__ __align__(16) char sm[];
    const uint32_t q_u32  = (uint32_t)__cvta_generic_to_shared(sm);
    const uint32_t kv_u32 = q_u32 + QTILE_B;

    const int tid  = threadIdx.x;
    const int lane = tid & 31;
    const int wid  = tid >> 5;           // 0..7
    const int g  = lane >> 2;
    const int tg = lane & 3;
    const int rbase = wid * 16;          // warp owns rows rbase..rbase+15
    const int qblk = (int)gridDim.x - 1 - (int)blockIdx.x;   // LPT: heavy CTAs first
    const int q0 = qblk * 128;
    const int h = blockIdx.y, b = blockIdx.z;
    const size_t base = (size_t)b * Sdim * HD + (size_t)h * Ddim;

    // LDSM lane bases
    const uint32_t q_loff = (uint32_t)(rbase + (lane & 15)) * TROW + (uint32_t)((lane >> 4) << 4);
    const uint32_t b_loff = (uint32_t)((lane & 7) + ((lane >> 4) << 3)) * TROW
                          + (uint32_t)(((lane >> 3) & 1) << 4);
    const uint32_t v_loff = (uint32_t)((lane & 7) + (((lane >> 3) & 1) << 3)) * TROW
                          + (uint32_t)((lane >> 4) << 4);

    const int ntiles = (q0 >> 6) + 2;

    auto issue_kv = [&](int t) {
        const uint32_t kvb = kv_u32 + (uint32_t)(t % 3) * KVBUF;
        const int jr = t * 64;
        #pragma unroll
        for (int i = 0; i < 4; i++) {
            const int idx = tid + i * 256;
            const int j = idx & 7;
            if (idx < 512) {
                const int r = idx >> 3;
                cp16(kvb + r * TROW + j * 16u, K + base + (size_t)(jr + r) * HD + j * 8);
            } else {
                const int r = (idx - 512) >> 3;
                cp16(kvb + KVTILE_B + r * TROW + j * 16u,
                     V + base + (size_t)(jr + r) * HD + j * 8);
            }
        }
    };

    // prologue: G0 = Q(128 rows) + KV tile 0 ; G1 = KV tile 1 (always exists)
    #pragma unroll
    for (int i = 0; i < 4; i++) {
        const int idx = tid + i * 256;
        const int r = idx >> 3, j = idx & 7;
        cp16(q_u32 + r * TROW + j * 16u, Q + base + (size_t)(q0 + r) * HD + j * 8);
    }
    issue_kv(0);
    cp_commit();
    issue_kv(1);
    cp_commit();

    float m1 = -1e30f, m2 = -1e30f, l1 = 0.f, l2 = 0.f;
    float o[8][4] = {};
    const int grow_base = q0 + rbase;    // warp's first global query row
    const int grow1 = grow_base + g, grow2 = grow1 + 8;

    for (int jt = 0; jt < ntiles; jt++) {
        cp_wait<1>();
        __syncthreads();     // tile jt ready; all warps done with tile jt-1's buffer

        if (jt + 2 < ntiles) issue_kv(jt + 2);
        cp_commit();

        const int j0 = jt * 64;
        const uint32_t kb32 = kv_u32 + (uint32_t)(jt % 3) * KVBUF;
        const uint32_t vb32 = kb32 + KVTILE_B;
        const bool active = (j0 <= grow_base + 15);   // warp-uniform

        if (active) {
            // S = Q K^T (16 rows x 64 cols), log2 domain
            float s[8][4] = {};
            #pragma unroll
            for (int kb = 0; kb < 4; kb++) {
                uint32_t af[4];
                ldsm4(af, q_u32 + q_loff + kb * 32u);
                #pragma unroll
                for (int nb = 0; nb < 4; nb++) {
                    uint32_t bf[4];
                    ldsm4(bf, kb32 + b_loff + (uint32_t)(nb * 16) * TROW + kb * 32u);
                    mma_bf16(s[nb * 2],     af[0], af[1], af[2], af[3], bf[0], bf[1]);
                    mma_bf16(s[nb * 2 + 1], af[0], af[1], af[2], af[3], bf[2], bf[3]);
                }
            }

            // online softmax (base-2); p stored back into s
            const bool diag = (j0 + 63 > grow_base);
            float rm1 = -1e30f, rm2 = -1e30f;
            #pragma unroll
            for (int nt = 0; nt < 8; nt++) {
                if (diag) {
                    const int c0 = j0 + nt * 8 + 2 * tg;
                    if (c0     > grow1) s[nt][0] = -1e30f;
                    if (c0 + 1 > grow1) s[nt][1] = -1e30f;
                    if (c0     > grow2) s[nt][2] = -1e30f;
                    if (c0 + 1 > grow2) s[nt][3] = -1e30f;
                }
                rm1 = fmaxf(rm1, fmaxf(s[nt][0], s[nt][1]));
                rm2 = fmaxf(rm2, fmaxf(s[nt][2], s[nt][3]));
            }
            rm1 = fmaxf(rm1, __shfl_xor_sync(0xffffffffu, rm1, 1));
            rm1 = fmaxf(rm1, __shfl_xor_sync(0xffffffffu, rm1, 2));
            rm2 = fmaxf(rm2, __shfl_xor_sync(0xffffffffu, rm2, 1));
            rm2 = fmaxf(rm2, __shfl_xor_sync(0xffffffffu, rm2, 2));

            const float mn1 = fmaxf(m1, rm1), mn2 = fmaxf(m2, rm2);
            const float sc1 = ex2f(m1 - mn1), sc2 = ex2f(m2 - mn2);
            m1 = mn1; m2 = mn2;

            float sum1 = 0.f, sum2 = 0.f;
            #pragma unroll
            for (int nt = 0; nt < 8; nt++) {
                s[nt][0] = ex2f(s[nt][0] - mn1);
                s[nt][1] = ex2f(s[nt][1] - mn1);
                s[nt][2] = ex2f(s[nt][2] - mn2);
                s[nt][3] = ex2f(s[nt][3] - mn2);
                sum1 += s[nt][0] + s[nt][1];
                sum2 += s[nt][2] + s[nt][3];
            }
            sum1 += __shfl_xor_sync(0xffffffffu, sum1, 1);
            sum1 += __shfl_xor_sync(0xffffffffu, sum1, 2);
            sum2 += __shfl_xor_sync(0xffffffffu, sum2, 1);
            sum2 += __shfl_xor_sync(0xffffffffu, sum2, 2);
            l1 = l1 * sc1 + sum1;
            l2 = l2 * sc2 + sum2;

            #pragma unroll
            for (int nt = 0; nt < 8; nt++) {
                o[nt][0] *= sc1; o[nt][1] *= sc1;
                o[nt][2] *= sc2; o[nt][3] *= sc2;
            }

            // O += P V : P A-fragments built directly from S C-fragments
            #pragma unroll
            for (int kb = 0; kb < 4; kb++) {
                uint32_t pa[4];
                pa[0] = packbf(s[2 * kb][0],     s[2 * kb][1]);
                pa[1] = packbf(s[2 * kb][2],     s[2 * kb][3]);
                pa[2] = packbf(s[2 * kb + 1][0], s[2 * kb + 1][1]);
                pa[3] = packbf(s[2 * kb + 1][2], s[2 * kb + 1][3]);
                #pragma unroll
                for (int nb = 0; nb < 4; nb++) {
                    uint32_t bf[4];
                    ldsm4t(bf, vb32 + v_loff + (uint32_t)(kb * 16) * TROW + nb * 32u);
                    mma_bf16(o[nb * 2],     pa[0], pa[1], pa[2], pa[3], bf[0], bf[1]);
                    mma_bf16(o[nb * 2 + 1], pa[0], pa[1], pa[2], pa[3], bf[2], bf[3]);
                }
            }
        }
    }

    const float inv1 = 1.0f / l1;
    const float inv2 = 1.0f / l2;
    #pragma unroll
    for (int nt = 0; nt < 8; nt++) {
        const int cb = nt * 8 + 2 * tg;
        *reinterpret_cast<uint32_t*>(O + base + (size_t)grow1 * HD + cb) =
            packbf(o[nt][0] * inv1, o[nt][1] * inv1);
        *reinterpret_cast<uint32_t*>(O + base + (size_t)grow2 * HD + cb) =
            packbf(o[nt][2] * inv2, o[nt][3] * inv2);
    }
}

// ---------------- launch ----------------------------------------------------
extern "C" void kernel_launch(void* const* d_in, const int* in_sizes, int n_in,
                              void* d_out, int out_size) {
    const float* x     = (const float*)d_in[0];
    const float* gamma = (const float*)d_in[1];
    const float* beta  = (const float*)d_in[2];
    const float* Wq    = (const float*)d_in[3];
    const float* bq    = (const float*)d_in[4];
    const float* Wk    = (const float*)d_in[5];
    const float* bk    = (const float*)d_in[6];
    const float* Wv    = (const float*)d_in[7];
    const float* bv    = (const float*)d_in[8];
    const float* Wo    = (const float*)d_in[9];
    const float* bo    = (const float*)d_in[10];
    float* out = (float*)d_out;

    __nv_bfloat16 *xn, *qp, *kp, *vp, *ao, *wt;
    cudaGetSymbolAddress((void**)&xn, g_xn);
    cudaGetSymbolAddress((void**)&qp, g_q);
    cudaGetSymbolAddress((void**)&kp, g_k);
    cudaGetSymbolAddress((void**)&vp, g_v);
    cudaGetSymbolAddress((void**)&ao, g_ao);
    cudaGetSymbolAddress((void**)&wt, g_wt);

    prep_kernel<<<Mrows + 4096, 256>>>(x, gamma, beta, xn, Wq, Wk, Wv, Wo, wt);

    cudaFuncSetAttribute(qkv_gemm_kernel, cudaFuncAttributeMaxDynamicSharedMemorySize,
                         GEMM_SMEM_BYTES);
    cudaFuncSetAttribute(o_gemm_kernel, cudaFuncAttributeMaxDynamicSharedMemorySize,
                         GEMM_SMEM_BYTES);

    qkv_gemm_kernel<<<dim3(24, Mrows / 128), 256, GEMM_SMEM_BYTES>>>(
        xn, wt, bq, bk, bv, qp, kp, vp);

    cudaFuncSetAttribute(attn_bf16_kernel, cudaFuncAttributeMaxDynamicSharedMemorySize,
                         ATTN_SMEM_BYTES);
    attn_bf16_kernel<<<dim3(Sdim / 128, Hdim, Bdim), 256, ATTN_SMEM_BYTES>>>(qp, kp, vp, ao);

    o_gemm_kernel<<<dim3(8, Mrows / 128), 256, GEMM_SMEM_BYTES>>>(ao, wt, bo, x, out);
}

// round 13
// speedup vs baseline: 1.1210x; 1.0214x over previous
#include <cuda_runtime.h>
#include <cuda_bf16.h>
#include <math.h>
#include <stdint.h>

#define Bdim 4
#define Sdim 2048
#define Edim 1024
#define Hdim 16
#define Ddim 64
#define Mrows (Bdim * Sdim)          // 8192
#define HD (Hdim * Ddim)             // 1024
#define GK 1024

// ---------------- scratch (static device globals; no allocs) ----------------
__device__ __nv_bfloat16 g_xn[Mrows * Edim];
__device__ __nv_bfloat16 g_q [Mrows * HD];
__device__ __nv_bfloat16 g_k [Mrows * HD];
__device__ __nv_bfloat16 g_v [Mrows * HD];
__device__ __nv_bfloat16 g_ao[Mrows * HD];
__device__ __nv_bfloat16 g_wt[4 * GK * GK];   // transposed weights [N][K] bf16

// ---------------- helpers ----------------------------------------------------
__device__ __forceinline__ uint32_t packbf(float lo, float hi) {
    uint32_t d;
    asm("cvt.rn.bf16x2.f32 %0, %1, %2;" : "=r"(d) : "f"(hi), "f"(lo));
    return d;
}
__device__ __forceinline__ float ex2f(float x) {
    float y;
    asm("ex2.approx.f32 %0, %1;" : "=f"(y) : "f"(x));
    return y;
}

// D(16x8) += A(16x16,row) * B(16x8,col)  bf16 -> fp32
__device__ __forceinline__ void mma_bf16(float c[4],
                                         uint32_t a0, uint32_t a1, uint32_t a2, uint32_t a3,
                                         uint32_t b0, uint32_t b1) {
    asm volatile(
        "mma.sync.aligned.m16n8k16.row.col.f32.bf16.bf16.f32 "
        "{%0,%1,%2,%3}, {%4,%5,%6,%7}, {%8,%9}, {%0,%1,%2,%3};\n"
        : "+f"(c[0]), "+f"(c[1]), "+f"(c[2]), "+f"(c[3])
        : "r"(a0), "r"(a1), "r"(a2), "r"(a3), "r"(b0), "r"(b1));
}

__device__ __forceinline__ void ldsm4(uint32_t r[4], uint32_t addr) {
    asm volatile("ldmatrix.sync.aligned.m8n8.x4.shared.b16 {%0,%1,%2,%3}, [%4];"
                 : "=r"(r[0]), "=r"(r[1]), "=r"(r[2]), "=r"(r[3])
                 : "r"(addr));
}
__device__ __forceinline__ void ldsm4t(uint32_t r[4], uint32_t addr) {
    asm volatile("ldmatrix.sync.aligned.m8n8.x4.trans.shared.b16 {%0,%1,%2,%3}, [%4];"
                 : "=r"(r[0]), "=r"(r[1]), "=r"(r[2]), "=r"(r[3])
                 : "r"(addr));
}

__device__ __forceinline__ void cp16(uint32_t dst, const void* src) {
    asm volatile("cp.async.cg.shared.global [%0], [%1], 16;" :: "r"(dst), "l"(src));
}
__device__ __forceinline__ void cp_commit() {
    asm volatile("cp.async.commit_group;");
}
template <int N>
__device__ __forceinline__ void cp_wait() {
    asm volatile("cp.async.wait_group %0;" :: "n"(N));
}

// ---------------- merged prep: LayerNorm (blocks 0..8191) + transpose -------
// LN: fp32 x -> bf16 xn. Transpose: W[K,N] fp32 -> WT[N,K] bf16.
__global__ void __launch_bounds__(256) prep_kernel(const float* __restrict__ x,
                                                   const float* __restrict__ gamma,
                                                   const float* __restrict__ beta,
                                                   __nv_bfloat16* __restrict__ y,
                                                   const float* __restrict__ Wq,
                                                   const float* __restrict__ Wk,
                                                   const float* __restrict__ Wv,
                                                   const float* __restrict__ Wo,
                                                   __nv_bfloat16* __restrict__ wt) {
    __shared__ float tsh[32][33];
    const int tid = threadIdx.x;

    if (blockIdx.x < Mrows) {
        // ---------------- LayerNorm ----------------
        const int row = blockIdx.x;
        const float4 xv = reinterpret_cast<const float4*>(x + (size_t)row * Edim)[tid];
        float s  = xv.x + xv.y + xv.z + xv.w;
        float ss = xv.x * xv.x + xv.y * xv.y + xv.z * xv.z + xv.w * xv.w;
        #pragma unroll
        for (int m = 16; m; m >>= 1) {
            s  += __shfl_xor_sync(0xffffffffu, s,  m);
            ss += __shfl_xor_sync(0xffffffffu, ss, m);
        }
        __shared__ float sh_s[8], sh_ss[8];
        __shared__ float s_mu, s_rstd;
        const int w = tid >> 5, l = tid & 31;
        if (l == 0) { sh_s[w] = s; sh_ss[w] = ss; }
        __syncthreads();
        if (w == 0) {
            float a = (l < 8) ? sh_s[l]  : 0.f;
            float c = (l < 8) ? sh_ss[l] : 0.f;
            #pragma unroll
            for (int m = 4; m; m >>= 1) {
                a += __shfl_xor_sync(0xffffffffu, a, m);
                c += __shfl_xor_sync(0xffffffffu, c, m);
            }
            if (l == 0) {
                float mu  = a * (1.0f / Edim);
                float var = c * (1.0f / Edim) - mu * mu;
                s_mu = mu;
                s_rstd = rsqrtf(var + 1e-5f);
            }
        }
        __syncthreads();
        const float mu = s_mu, rstd = s_rstd;
        const float4 gv = reinterpret_cast<const float4*>(gamma)[tid];
        const float4 bv = reinterpret_cast<const float4*>(beta)[tid];
        uint2 o2;
        o2.x = packbf((xv.x - mu) * rstd * gv.x + bv.x, (xv.y - mu) * rstd * gv.y + bv.y);
        o2.y = packbf((xv.z - mu) * rstd * gv.z + bv.z, (xv.w - mu) * rstd * gv.w + bv.w);
        *reinterpret_cast<uint2*>(y + (size_t)row * Edim + tid * 4) = o2;
    } else {
        // ---------------- weight transpose ----------------
        const int bid = blockIdx.x - Mrows;
        const int z = bid >> 10;
        const int rem = bid & 1023;
        const int x0 = (rem & 31) << 5, y0 = (rem >> 5) << 5;
        const float* W = (z == 0) ? Wq : (z == 1) ? Wk : (z == 2) ? Wv : Wo;
        __nv_bfloat16* T = wt + (size_t)z * GK * GK;
        const int tx = tid & 31, ty = tid >> 5;   // 32x8
        #pragma unroll
        for (int i = 0; i < 32; i += 8)
            tsh[ty + i][tx] = W[(size_t)(y0 + ty + i) * GK + x0 + tx];
        __syncthreads();
        #pragma unroll
        for (int i = 0; i < 32; i += 8)
            T[(size_t)(x0 + ty + i) * GK + y0 + tx] = __float2bfloat16(tsh[tx][ty + i]);
    }
}

// ---------------- bf16 GEMM: 128x128 tile, BK=32, 4-stage cp.async ----------
// ONE __syncthreads per mainloop iteration (trailing barrier is redundant:
// next iteration's top barrier orders reads-of-stage before its overwrite).
#define BK 32
#define ROWB 80u
#define STG_A 0u
#define STG_B 10240u
#define STAGE_BYTES 20480u
#define GSTAGES 4
#define GEMM_SMEM_BYTES (GSTAGES * STAGE_BYTES)   // 81920

template <bool BF16OUT>
__device__ __forceinline__ void gemm_body(const __nv_bfloat16* __restrict__ A,
                                          const __nv_bfloat16* __restrict__ WT,
                                          const float* __restrict__ bias,
                                          const float* __restrict__ res,
                                          void* __restrict__ C,
                                          int bx, int by, float oscale) {
    extern __shared__ __align__(16) char smem[];
    const uint32_t s0 = (uint32_t)__cvta_generic_to_shared(smem);

    const int tid  = threadIdx.x;
    const int lane = tid & 31;
    const int wid  = tid >> 5;
    const int g  = lane >> 2;
    const int tg = lane & 3;
    const int wm = wid >> 2;
    const int wn = wid & 3;
    const int row0 = by * 128;
    const int col0 = bx * 128;
    const int N = 1024;

    const uint32_t a_off = STG_A + (uint32_t)(wm * 64 + (lane & 15)) * ROWB
                                 + (uint32_t)((lane >> 4) << 4);
    const uint32_t b_off = STG_B + (uint32_t)(wn * 32 + (lane & 7) + ((lane >> 4) << 3)) * ROWB
                                 + (uint32_t)(((lane >> 3) & 1) << 4);

    auto issue_tile = [&](int t) {
        const uint32_t sb = s0 + (uint32_t)(t % GSTAGES) * STAGE_BYTES;
        const int gk = t * BK;
        #pragma unroll
        for (int i = 0; i < 4; i++) {
            const int idx = tid + i * 256;
            const int r = (idx & 511) >> 2;
            const int j = idx & 3;
            if (idx < 512)
                cp16(sb + STG_A + r * ROWB + j * 16u,
                     A + (size_t)(row0 + r) * GK + gk + j * 8);
            else
                cp16(sb + STG_B + r * ROWB + j * 16u,
                     WT + (size_t)(col0 + r) * GK + gk + j * 8);
        }
        cp_commit();
    };

    issue_tile(0);
    issue_tile(1);
    issue_tile(2);

    float acc[4][4][4] = {};
    const int NIT = GK / BK;     // 32

    for (int it = 0; it < NIT; it++) {
        cp_wait<GSTAGES - 2>();
        __syncthreads();   // stage it ready AND all warps done reading stage (it+3)%4

        if (it + GSTAGES - 1 < NIT) issue_tile(it + GSTAGES - 1);
        else cp_commit();

        const uint32_t sb = s0 + (uint32_t)(it % GSTAGES) * STAGE_BYTES;
        #pragma unroll
        for (int kb = 0; kb < 2; kb++) {
            uint32_t af[4][4], bf[2][4];
            #pragma unroll
            for (int mi = 0; mi < 4; mi++)
                ldsm4(af[mi], sb + a_off + (uint32_t)(mi * 16) * ROWB + kb * 32u);
            #pragma unroll
            for (int nb = 0; nb < 2; nb++)
                ldsm4(bf[nb], sb + b_off + (uint32_t)(nb * 16) * ROWB + kb * 32u);
            #pragma unroll
            for (int mi = 0; mi < 4; mi++)
                #pragma unroll
                for (int nb = 0; nb < 2; nb++) {
                    mma_bf16(acc[mi][nb * 2],     af[mi][0], af[mi][1], af[mi][2], af[mi][3],
                             bf[nb][0], bf[nb][1]);
                    mma_bf16(acc[mi][nb * 2 + 1], af[mi][0], af[mi][1], af[mi][2], af[mi][3],
                             bf[nb][2], bf[nb][3]);
                }
        }
        // no trailing __syncthreads: next iteration's barrier provides the ordering
    }

    #pragma unroll
    for (int mi = 0; mi < 4; mi++) {
        const int r1 = row0 + wm * 64 + mi * 16 + g;
        const int r2 = r1 + 8;
        #pragma unroll
        for (int ni = 0; ni < 4; ni++) {
            const int cb = col0 + wn * 32 + ni * 8 + 2 * tg;
            float v0 = (acc[mi][ni][0] + bias[cb])     * oscale;
            float v1 = (acc[mi][ni][1] + bias[cb + 1]) * oscale;
            float v2 = (acc[mi][ni][2] + bias[cb])     * oscale;
            float v3 = (acc[mi][ni][3] + bias[cb + 1]) * oscale;
            if (BF16OUT) {
                ((uint32_t*)C)[(size_t)r1 * (N / 2) + (cb >> 1)] = packbf(v0, v1);
                ((uint32_t*)C)[(size_t)r2 * (N / 2) + (cb >> 1)] = packbf(v2, v3);
            } else {
                const float2 r1v = *reinterpret_cast<const float2*>(res + (size_t)r1 * N + cb);
                const float2 r2v = *reinterpret_cast<const float2*>(res + (size_t)r2 * N + cb);
                float2 w1; w1.x = v0 + r1v.x; w1.y = v1 + r1v.y;
                float2 w2; w2.x = v2 + r2v.x; w2.y = v3 + r2v.y;
                *reinterpret_cast<float2*>((float*)C + (size_t)r1 * N + cb) = w1;
                *reinterpret_cast<float2*>((float*)C + (size_t)r2 * N + cb) = w2;
            }
        }
    }
}

// fused QKV: grid (24, 64); Q output pre-scaled by log2(e)/sqrt(D)
__global__ void __launch_bounds__(256, 2) qkv_gemm_kernel(const __nv_bfloat16* __restrict__ A,
                                                          const __nv_bfloat16* __restrict__ wt,
                                                          const float* __restrict__ bq,
                                                          const float* __restrict__ bk,
                                                          const float* __restrict__ bv,
                                                          __nv_bfloat16* __restrict__ Cq,
                                                          __nv_bfloat16* __restrict__ Ck,
                                                          __nv_bfloat16* __restrict__ Cv) {
    const int mat = blockIdx.x >> 3;
    const int bx  = blockIdx.x & 7;
    const __nv_bfloat16* WT = wt + (size_t)mat * GK * GK;
    const float* bias = (mat == 0) ? bq : (mat == 1) ? bk : bv;
    __nv_bfloat16* C  = (mat == 0) ? Cq : (mat == 1) ? Ck : Cv;
    const float sc = (mat == 0) ? 0.1803368801111354f : 1.0f;   // 0.125 * log2(e)
    gemm_body<true>(A, WT, bias, nullptr, C, bx, blockIdx.y, sc);
}

__global__ void __launch_bounds__(256, 2) o_gemm_kernel(const __nv_bfloat16* __restrict__ A,
                                                        const __nv_bfloat16* __restrict__ wt,
                                                        const float* __restrict__ bo,
                                                        const float* __restrict__ res,
                                                        float* __restrict__ out) {
    gemm_body<false>(A, wt + (size_t)3 * GK * GK, bo, res, out, blockIdx.x, blockIdx.y, 1.0f);
}

// ---------------- Flash attention (causal), bf16, in-register P -------------
// grid (S/128, H, B), 256 threads (8 warps). Warp w owns 16 query rows.
// Scores in log2 domain (Q pre-scaled); softmax uses ex2.
// smem: Q tile + 3-deep KV ring => ONE __syncthreads per tile.
#define TROW 144u
#define QTILE_B (128u * TROW)            // 18432
#define KVTILE_B (64u * TROW)            // 9216
#define KVBUF (2u * KVTILE_B)            // K+V per buffer: 18432
#define ATTN_SMEM_BYTES (QTILE_B + 3 * KVBUF)   // 73728

__global__ void __launch_bounds__(256, 2) attn_bf16_kernel(const __nv_bfloat16* __restrict__ Q,
                                                           const __nv_bfloat16* __restrict__ K,
                                                           const __nv_bfloat16* __restrict__ V,
                                                           __nv_bfloat16* __restrict__ O) {
    extern __shared__ __align__(16) char sm[];
    const uint32_t q_u32  = (uint32_t)__cvta_generic_to_shared(sm);
    const uint32_t kv_u32 = q_u32 + QTILE_B;

    const int tid  = threadIdx.x;
    const int lane = tid & 31;
    const int wid  = tid >> 5;           // 0..7
    const int g  = lane >> 2;
    const int tg = lane & 3;
    const int rbase = wid * 16;          // warp owns rows rbase..rbase+15
    const int qblk = (int)gridDim.x - 1 - (int)blockIdx.x;   // LPT: heavy CTAs first
    const int q0 = qblk * 128;
    const int h = blockIdx.y, b = blockIdx.z;
    const size_t base = (size_t)b * Sdim * HD + (size_t)h * Ddim;

    // LDSM lane bases
    const uint32_t q_loff = (uint32_t)(rbase + (lane & 15)) * TROW + (uint32_t)((lane >> 4) << 4);
    const uint32_t b_loff = (uint32_t)((lane & 7) + ((lane >> 4) << 3)) * TROW
                          + (uint32_t)(((lane >> 3) & 1) << 4);
    const uint32_t v_loff = (uint32_t)((lane & 7) + (((lane >> 3) & 1) << 3)) * TROW
                          + (uint32_t)((lane >> 4) << 4);

    const int ntiles = (q0 >> 6) + 2;

    auto issue_kv = [&](int t) {
        const uint32_t kvb = kv_u32 + (uint32_t)(t % 3) * KVBUF;
        const int jr = t * 64;
        #pragma unroll
        for (int i = 0; i < 4; i++) {
            const int idx = tid + i * 256;
            const int j = idx & 7;
            if (idx < 512) {
                const int r = idx >> 3;
                cp16(kvb + r * TROW + j * 16u, K + base + (size_t)(jr + r) * HD + j * 8);
            } else {
                const int r = (idx - 512) >> 3;
                cp16(kvb + KVTILE_B + r * TROW + j * 16u,
                     V + base + (size_t)(jr + r) * HD + j * 8);
            }
        }
    };

    // prologue: G0 = Q(128 rows) + KV tile 0 ; G1 = KV tile 1 (always exists)
    #pragma unroll
    for (int i = 0; i < 4; i++) {
        const int idx = tid + i * 256;
        const int r = idx >> 3, j = idx & 7;
        cp16(q_u32 + r * TROW + j * 16u, Q + base + (size_t)(q0 + r) * HD + j * 8);
    }
    issue_kv(0);
    cp_commit();
    issue_kv(1);
    cp_commit();

    float m1 = -1e30f, m2 = -1e30f, l1 = 0.f, l2 = 0.f;
    float o[8][4] = {};
    const int grow_base = q0 + rbase;    // warp's first global query row
    const int grow1 = grow_base + g, grow2 = grow1 + 8;

    for (int jt = 0; jt < ntiles; jt++) {
        cp_wait<1>();
        __syncthreads();     // tile jt ready; all warps done with tile jt-1's buffer

        if (jt + 2 < ntiles) issue_kv(jt + 2);
        cp_commit();

        const int j0 = jt * 64;
        const uint32_t kb32 = kv_u32 + (uint32_t)(jt % 3) * KVBUF;
        const uint32_t vb32 = kb32 + KVTILE_B;
        const bool active = (j0 <= grow_base + 15);   // warp-uniform

        if (active) {
            // S = Q K^T (16 rows x 64 cols), log2 domain
            float s[8][4] = {};
            #pragma unroll
            for (int kb = 0; kb < 4; kb++) {
                uint32_t af[4];
                ldsm4(af, q_u32 + q_loff + kb * 32u);
                #pragma unroll
                for (int nb = 0; nb < 4; nb++) {
                    uint32_t bf[4];
                    ldsm4(bf, kb32 + b_loff + (uint32_t)(nb * 16) * TROW + kb * 32u);
                    mma_bf16(s[nb * 2],     af[0], af[1], af[2], af[3], bf[0], bf[1]);
                    mma_bf16(s[nb * 2 + 1], af[0], af[1], af[2], af[3], bf[2], bf[3]);
                }
            }

            // online softmax (base-2); p stored back into s
            const bool diag = (j0 + 63 > grow_base);
            float rm1 = -1e30f, rm2 = -1e30f;
            #pragma unroll
            for (int nt = 0; nt < 8; nt++) {
                if (diag) {
                    const int c0 = j0 + nt * 8 + 2 * tg;
                    if (c0     > grow1) s[nt][0] = -1e30f;
                    if (c0 + 1 > grow1) s[nt][1] = -1e30f;
                    if (c0     > grow2) s[nt][2] = -1e30f;
                    if (c0 + 1 > grow2) s[nt][3] = -1e30f;
                }
                rm1 = fmaxf(rm1, fmaxf(s[nt][0], s[nt][1]));
                rm2 = fmaxf(rm2, fmaxf(s[nt][2], s[nt][3]));
            }
            rm1 = fmaxf(rm1, __shfl_xor_sync(0xffffffffu, rm1, 1));
            rm1 = fmaxf(rm1, __shfl_xor_sync(0xffffffffu, rm1, 2));
            rm2 = fmaxf(rm2, __shfl_xor_sync(0xffffffffu, rm2, 1));
            rm2 = fmaxf(rm2, __shfl_xor_sync(0xffffffffu, rm2, 2));

            const float mn1 = fmaxf(m1, rm1), mn2 = fmaxf(m2, rm2);
            const float sc1 = ex2f(m1 - mn1), sc2 = ex2f(m2 - mn2);
            m1 = mn1; m2 = mn2;

            float sum1 = 0.f, sum2 = 0.f;
            #pragma unroll
            for (int nt = 0; nt < 8; nt++) {
                s[nt][0] = ex2f(s[nt][0] - mn1);
                s[nt][1] = ex2f(s[nt][1] - mn1);
                s[nt][2] = ex2f(s[nt][2] - mn2);
                s[nt][3] = ex2f(s[nt][3] - mn2);
                sum1 += s[nt][0] + s[nt][1];
                sum2 += s[nt][2] + s[nt][3];
            }
            sum1 += __shfl_xor_sync(0xffffffffu, sum1, 1);
            sum1 += __shfl_xor_sync(0xffffffffu, sum1, 2);
            sum2 += __shfl_xor_sync(0xffffffffu, sum2, 1);
            sum2 += __shfl_xor_sync(0xffffffffu, sum2, 2);
            l1 = l1 * sc1 + sum1;
            l2 = l2 * sc2 + sum2;

            #pragma unroll
            for (int nt = 0; nt < 8; nt++) {
                o[nt][0] *= sc1; o[nt][1] *= sc1;
                o[nt][2] *= sc2; o[nt][3] *= sc2;
            }

            // O += P V : P A-fragments built directly from S C-fragments
            #pragma unroll
            for (int kb = 0; kb < 4; kb++) {
                uint32_t pa[4];
                pa[0] = packbf(s[2 * kb][0],     s[2 * kb][1]);
                pa[1] = packbf(s[2 * kb][2],     s[2 * kb][3]);
                pa[2] = packbf(s[2 * kb + 1][0], s[2 * kb + 1][1]);
                pa[3] = packbf(s[2 * kb + 1][2], s[2 * kb + 1][3]);
                #pragma unroll
                for (int nb = 0; nb < 4; nb++) {
                    uint32_t bf[4];
                    ldsm4t(bf, vb32 + v_loff + (uint32_t)(kb * 16) * TROW + nb * 32u);
                    mma_bf16(o[nb * 2],     pa[0], pa[1], pa[2], pa[3], bf[0], bf[1]);
                    mma_bf16(o[nb * 2 + 1], pa[0], pa[1], pa[2], pa[3], bf[2], bf[3]);
                }
            }
        }
    }

    const float inv1 = 1.0f / l1;
    const float inv2 = 1.0f / l2;
    #pragma unroll
    for (int nt = 0; nt < 8; nt++) {
        const int cb = nt * 8 + 2 * tg;
        *reinterpret_cast<uint32_t*>(O + base + (size_t)grow1 * HD + cb) =
            packbf(o[nt][0] * inv1, o[nt][1] * inv1);
        *reinterpret_cast<uint32_t*>(O + base + (size_t)grow2 * HD + cb) =
            packbf(o[nt][2] * inv2, o[nt][3] * inv2);
    }
}

// ---------------- launch ----------------------------------------------------
extern "C" void kernel_launch(void* const* d_in, const int* in_sizes, int n_in,
                              void* d_out, int out_size) {
    const float* x     = (const float*)d_in[0];
    const float* gamma = (const float*)d_in[1];
    const float* beta  = (const float*)d_in[2];
    const float* Wq    = (const float*)d_in[3];
    const float* bq    = (const float*)d_in[4];
    const float* Wk    = (const float*)d_in[5];
    const float* bk    = (const float*)d_in[6];
    const float* Wv    = (const float*)d_in[7];
    const float* bv    = (const float*)d_in[8];
    const float* Wo    = (const float*)d_in[9];
    const float* bo    = (const float*)d_in[10];
    float* out = (float*)d_out;

    __nv_bfloat16 *xn, *qp, *kp, *vp, *ao, *wt;
    cudaGetSymbolAddress((void**)&xn, g_xn);
    cudaGetSymbolAddress((void**)&qp, g_q);
    cudaGetSymbolAddress((void**)&kp, g_k);
    cudaGetSymbolAddress((void**)&vp, g_v);
    cudaGetSymbolAddress((void**)&ao, g_ao);
    cudaGetSymbolAddress((void**)&wt, g_wt);

    prep_kernel<<<Mrows + 4096, 256>>>(x, gamma, beta, xn, Wq, Wk, Wv, Wo, wt);

    cudaFuncSetAttribute(qkv_gemm_kernel, cudaFuncAttributeMaxDynamicSharedMemorySize,
                         GEMM_SMEM_BYTES);
    cudaFuncSetAttribute(o_gemm_kernel, cudaFuncAttributeMaxDynamicSharedMemorySize,
                         GEMM_SMEM_BYTES);

    qkv_gemm_kernel<<<dim3(24, Mrows / 128), 256, GEMM_SMEM_BYTES>>>(
        xn, wt, bq, bk, bv, qp, kp, vp);

    cudaFuncSetAttribute(attn_bf16_kernel, cudaFuncAttributeMaxDynamicSharedMemorySize,
                         ATTN_SMEM_BYTES);
    attn_bf16_kernel<<<dim3(Sdim / 128, Hdim, Bdim), 256, ATTN_SMEM_BYTES>>>(qp, kp, vp, ao);

    o_gemm_kernel<<<dim3(8, Mrows / 128), 256, GEMM_SMEM_BYTES>>>(ao, wt, bo, x, out);
}

// round 14
// speedup vs baseline: 1.1999x; 1.0704x over previous
#include <cuda_runtime.h>
#include <cuda_bf16.h>
#include <math.h>
#include <stdint.h>

#define Bdim 4
#define Sdim 2048
#define Edim 1024
#define Hdim 16
#define Ddim 64
#define Mrows (Bdim * Sdim)          // 8192
#define HD (Hdim * Ddim)             // 1024
#define GK 1024

// ---------------- scratch (static device globals; no allocs) ----------------
__device__ __nv_bfloat16 g_xn[Mrows * Edim];
__device__ __nv_bfloat16 g_q [Mrows * HD];
__device__ __nv_bfloat16 g_k [Mrows * HD];
__device__ __nv_bfloat16 g_v [Mrows * HD];
__device__ __nv_bfloat16 g_ao[Mrows * HD];
__device__ __nv_bfloat16 g_wt[4 * GK * GK];   // transposed weights [N][K] bf16

// ---------------- helpers ----------------------------------------------------
__device__ __forceinline__ uint32_t packbf(float lo, float hi) {
    uint32_t d;
    asm("cvt.rn.bf16x2.f32 %0, %1, %2;" : "=r"(d) : "f"(hi), "f"(lo));
    return d;
}
__device__ __forceinline__ float ex2f(float x) {
    float y;
    asm("ex2.approx.f32 %0, %1;" : "=f"(y) : "f"(x));
    return y;
}

// D(16x8) += A(16x16,row) * B(16x8,col)  bf16 -> fp32
__device__ __forceinline__ void mma_bf16(float c[4],
                                         uint32_t a0, uint32_t a1, uint32_t a2, uint32_t a3,
                                         uint32_t b0, uint32_t b1) {
    asm volatile(
        "mma.sync.aligned.m16n8k16.row.col.f32.bf16.bf16.f32 "
        "{%0,%1,%2,%3}, {%4,%5,%6,%7}, {%8,%9}, {%0,%1,%2,%3};\n"
        : "+f"(c[0]), "+f"(c[1]), "+f"(c[2]), "+f"(c[3])
        : "r"(a0), "r"(a1), "r"(a2), "r"(a3), "r"(b0), "r"(b1));
}

__device__ __forceinline__ void ldsm4(uint32_t r[4], uint32_t addr) {
    asm volatile("ldmatrix.sync.aligned.m8n8.x4.shared.b16 {%0,%1,%2,%3}, [%4];"
                 : "=r"(r[0]), "=r"(r[1]), "=r"(r[2]), "=r"(r[3])
                 : "r"(addr));
}
__device__ __forceinline__ void ldsm4t(uint32_t r[4], uint32_t addr) {
    asm volatile("ldmatrix.sync.aligned.m8n8.x4.trans.shared.b16 {%0,%1,%2,%3}, [%4];"
                 : "=r"(r[0]), "=r"(r[1]), "=r"(r[2]), "=r"(r[3])
                 : "r"(addr));
}

__device__ __forceinline__ void cp16(uint32_t dst, const void* src) {
    asm volatile("cp.async.cg.shared.global [%0], [%1], 16;" :: "r"(dst), "l"(src));
}
__device__ __forceinline__ void cp_commit() {
    asm volatile("cp.async.commit_group;");
}
template <int N>
__device__ __forceinline__ void cp_wait() {
    asm volatile("cp.async.wait_group %0;" :: "n"(N));
}

// ---------------- merged prep: LayerNorm (blocks 0..8191) + transpose -------
__global__ void __launch_bounds__(256) prep_kernel(const float* __restrict__ x,
                                                   const float* __restrict__ gamma,
                                                   const float* __restrict__ beta,
                                                   __nv_bfloat16* __restrict__ y,
                                                   const float* __restrict__ Wq,
                                                   const float* __restrict__ Wk,
                                                   const float* __restrict__ Wv,
                                                   const float* __restrict__ Wo,
                                                   __nv_bfloat16* __restrict__ wt) {
    __shared__ float tsh[32][33];
    const int tid = threadIdx.x;

    if (blockIdx.x < Mrows) {
        const int row = blockIdx.x;
        const float4 xv = reinterpret_cast<const float4*>(x + (size_t)row * Edim)[tid];
        float s  = xv.x + xv.y + xv.z + xv.w;
        float ss = xv.x * xv.x + xv.y * xv.y + xv.z * xv.z + xv.w * xv.w;
        #pragma unroll
        for (int m = 16; m; m >>= 1) {
            s  += __shfl_xor_sync(0xffffffffu, s,  m);
            ss += __shfl_xor_sync(0xffffffffu, ss, m);
        }
        __shared__ float sh_s[8], sh_ss[8];
        __shared__ float s_mu, s_rstd;
        const int w = tid >> 5, l = tid & 31;
        if (l == 0) { sh_s[w] = s; sh_ss[w] = ss; }
        __syncthreads();
        if (w == 0) {
            float a = (l < 8) ? sh_s[l]  : 0.f;
            float c = (l < 8) ? sh_ss[l] : 0.f;
            #pragma unroll
            for (int m = 4; m; m >>= 1) {
                a += __shfl_xor_sync(0xffffffffu, a, m);
                c += __shfl_xor_sync(0xffffffffu, c, m);
            }
            if (l == 0) {
                float mu  = a * (1.0f / Edim);
                float var = c * (1.0f / Edim) - mu * mu;
                s_mu = mu;
                s_rstd = rsqrtf(var + 1e-5f);
            }
        }
        __syncthreads();
        const float mu = s_mu, rstd = s_rstd;
        const float4 gv = reinterpret_cast<const float4*>(gamma)[tid];
        const float4 bv = reinterpret_cast<const float4*>(beta)[tid];
        uint2 o2;
        o2.x = packbf((xv.x - mu) * rstd * gv.x + bv.x, (xv.y - mu) * rstd * gv.y + bv.y);
        o2.y = packbf((xv.z - mu) * rstd * gv.z + bv.z, (xv.w - mu) * rstd * gv.w + bv.w);
        *reinterpret_cast<uint2*>(y + (size_t)row * Edim + tid * 4) = o2;
    } else {
        const int bid = blockIdx.x - Mrows;
        const int z = bid >> 10;
        const int rem = bid & 1023;
        const int x0 = (rem & 31) << 5, y0 = (rem >> 5) << 5;
        const float* W = (z == 0) ? Wq : (z == 1) ? Wk : (z == 2) ? Wv : Wo;
        __nv_bfloat16* T = wt + (size_t)z * GK * GK;
        const int tx = tid & 31, ty = tid >> 5;   // 32x8
        #pragma unroll
        for (int i = 0; i < 32; i += 8)
            tsh[ty + i][tx] = W[(size_t)(y0 + ty + i) * GK + x0 + tx];
        __syncthreads();
        #pragma unroll
        for (int i = 0; i < 32; i += 8)
            T[(size_t)(x0 + ty + i) * GK + y0 + tx] = __float2bfloat16(tsh[tx][ty + i]);
    }
}

// ---------------- bf16 GEMM: 128x128 tile, BK=64, 3-stage cp.async ----------
// 16 mainloop iterations; ONE __syncthreads per iteration.
#define BK 64
#define ROWB 144u                          // 128B data + 16B pad
#define STG_A 0u
#define STG_B 18432u                       // 128 rows * 144B
#define STAGE_BYTES 36864u
#define GSTAGES 3
#define GEMM_SMEM_BYTES (GSTAGES * STAGE_BYTES)   // 110592

template <bool BF16OUT>
__device__ __forceinline__ void gemm_body(const __nv_bfloat16* __restrict__ A,
                                          const __nv_bfloat16* __restrict__ WT,
                                          const float* __restrict__ bias,
                                          const float* __restrict__ res,
                                          void* __restrict__ C,
                                          int bx, int by, float oscale) {
    extern __shared__ __align__(16) char smem[];
    const uint32_t s0 = (uint32_t)__cvta_generic_to_shared(smem);

    const int tid  = threadIdx.x;
    const int lane = tid & 31;
    const int wid  = tid >> 5;
    const int g  = lane >> 2;
    const int tg = lane & 3;
    const int wm = wid >> 2;
    const int wn = wid & 3;
    const int row0 = by * 128;
    const int col0 = bx * 128;
    const int N = 1024;

    const uint32_t a_off = STG_A + (uint32_t)(wm * 64 + (lane & 15)) * ROWB
                                 + (uint32_t)((lane >> 4) << 4);
    const uint32_t b_off = STG_B + (uint32_t)(wn * 32 + (lane & 7) + ((lane >> 4) << 3)) * ROWB
                                 + (uint32_t)(((lane >> 3) & 1) << 4);

    auto issue_tile = [&](int t) {
        const uint32_t sb = s0 + (uint32_t)(t % GSTAGES) * STAGE_BYTES;
        const int gk = t * BK;
        #pragma unroll
        for (int i = 0; i < 8; i++) {
            const int idx = tid + i * 256;       // 0..2047
            const int r = (idx >> 3) & 127;
            const int j = idx & 7;
            if (idx < 1024)
                cp16(sb + STG_A + r * ROWB + j * 16u,
                     A + (size_t)(row0 + r) * GK + gk + j * 8);
            else
                cp16(sb + STG_B + r * ROWB + j * 16u,
                     WT + (size_t)(col0 + r) * GK + gk + j * 8);
        }
        cp_commit();
    };

    issue_tile(0);
    issue_tile(1);

    float acc[4][4][4] = {};
    const int NIT = GK / BK;     // 16

    for (int it = 0; it < NIT; it++) {
        cp_wait<GSTAGES - 2>();
        __syncthreads();   // stage it ready AND all warps done reading stage (it+2)%3

        if (it + GSTAGES - 1 < NIT) issue_tile(it + GSTAGES - 1);
        else cp_commit();

        const uint32_t sb = s0 + (uint32_t)(it % GSTAGES) * STAGE_BYTES;
        #pragma unroll
        for (int kb = 0; kb < 4; kb++) {
            uint32_t af[4][4], bf[2][4];
            #pragma unroll
            for (int mi = 0; mi < 4; mi++)
                ldsm4(af[mi], sb + a_off + (uint32_t)(mi * 16) * ROWB + kb * 32u);
            #pragma unroll
            for (int nb = 0; nb < 2; nb++)
                ldsm4(bf[nb], sb + b_off + (uint32_t)(nb * 16) * ROWB + kb * 32u);
            #pragma unroll
            for (int mi = 0; mi < 4; mi++)
                #pragma unroll
                for (int nb = 0; nb < 2; nb++) {
                    mma_bf16(acc[mi][nb * 2],     af[mi][0], af[mi][1], af[mi][2], af[mi][3],
                             bf[nb][0], bf[nb][1]);
                    mma_bf16(acc[mi][nb * 2 + 1], af[mi][0], af[mi][1], af[mi][2], af[mi][3],
                             bf[nb][2], bf[nb][3]);
                }
        }
        // no trailing __syncthreads: next iteration's barrier provides the ordering
    }

    #pragma unroll
    for (int mi = 0; mi < 4; mi++) {
        const int r1 = row0 + wm * 64 + mi * 16 + g;
        const int r2 = r1 + 8;
        #pragma unroll
        for (int ni = 0; ni < 4; ni++) {
            const int cb = col0 + wn * 32 + ni * 8 + 2 * tg;
            float v0 = (acc[mi][ni][0] + bias[cb])     * oscale;
            float v1 = (acc[mi][ni][1] + bias[cb + 1]) * oscale;
            float v2 = (acc[mi][ni][2] + bias[cb])     * oscale;
            float v3 = (acc[mi][ni][3] + bias[cb + 1]) * oscale;
            if (BF16OUT) {
                ((uint32_t*)C)[(size_t)r1 * (N / 2) + (cb >> 1)] = packbf(v0, v1);
                ((uint32_t*)C)[(size_t)r2 * (N / 2) + (cb >> 1)] = packbf(v2, v3);
            } else {
                const float2 r1v = *reinterpret_cast<const float2*>(res + (size_t)r1 * N + cb);
                const float2 r2v = *reinterpret_cast<const float2*>(res + (size_t)r2 * N + cb);
                float2 w1; w1.x = v0 + r1v.x; w1.y = v1 + r1v.y;
                float2 w2; w2.x = v2 + r2v.x; w2.y = v3 + r2v.y;
                *reinterpret_cast<float2*>((float*)C + (size_t)r1 * N + cb) = w1;
                *reinterpret_cast<float2*>((float*)C + (size_t)r2 * N + cb) = w2;
            }
        }
    }
}

// fused QKV: grid (24, 64); Q output pre-scaled by log2(e)/sqrt(D)
__global__ void __launch_bounds__(256, 2) qkv_gemm_kernel(const __nv_bfloat16* __restrict__ A,
                                                          const __nv_bfloat16* __restrict__ wt,
                                                          const float* __restrict__ bq,
                                                          const float* __restrict__ bk,
                                                          const float* __restrict__ bv,
                                                          __nv_bfloat16* __restrict__ Cq,
                                                          __nv_bfloat16* __restrict__ Ck,
                                                          __nv_bfloat16* __restrict__ Cv) {
    const int mat = blockIdx.x >> 3;
    const int bx  = blockIdx.x & 7;
    const __nv_bfloat16* WT = wt + (size_t)mat * GK * GK;
    const float* bias = (mat == 0) ? bq : (mat == 1) ? bk : bv;
    __nv_bfloat16* C  = (mat == 0) ? Cq : (mat == 1) ? Ck : Cv;
    const float sc = (mat == 0) ? 0.1803368801111354f : 1.0f;   // 0.125 * log2(e)
    gemm_body<true>(A, WT, bias, nullptr, C, bx, blockIdx.y, sc);
}

__global__ void __launch_bounds__(256, 2) o_gemm_kernel(const __nv_bfloat16* __restrict__ A,
                                                        const __nv_bfloat16* __restrict__ wt,
                                                        const float* __restrict__ bo,
                                                        const float* __restrict__ res,
                                                        float* __restrict__ out) {
    gemm_body<false>(A, wt + (size_t)3 * GK * GK, bo, res, out, blockIdx.x, blockIdx.y, 1.0f);
}

// ---------------- Flash attention (causal), bf16, in-register P -------------
// grid (S/128, H, B), 256 threads (8 warps). Warp w owns 16 query rows.
// Scores in log2 domain (Q pre-scaled); softmax uses ex2.
// smem: Q tile + 3-deep KV ring => ONE __syncthreads per tile.
#define TROW 144u
#define QTILE_B (128u * TROW)            // 18432
#define KVTILE_B (64u * TROW)            // 9216
#define KVBUF (2u * KVTILE_B)            // K+V per buffer: 18432
#define ATTN_SMEM_BYTES (QTILE_B + 3 * KVBUF)   // 73728

__global__ void __launch_bounds__(256, 2) attn_bf16_kernel(const __nv_bfloat16* __restrict__ Q,
                                                           const __nv_bfloat16* __restrict__ K,
                                                           const __nv_bfloat16* __restrict__ V,
                                                           __nv_bfloat16* __restrict__ O) {
    extern __shared__ __align__(16) char sm[];
    const uint32_t q_u32  = (uint32_t)__cvta_generic_to_shared(sm);
    const uint32_t kv_u32 = q_u32 + QTILE_B;

    const int tid  = threadIdx.x;
    const int lane = tid & 31;
    const int wid  = tid >> 5;           // 0..7
    const int g  = lane >> 2;
    const int tg = lane & 3;
    const int rbase = wid * 16;          // warp owns rows rbase..rbase+15
    const int qblk = (int)gridDim.x - 1 - (int)blockIdx.x;   // LPT: heavy CTAs first
    const int q0 = qblk * 128;
    const int h = blockIdx.y, b = blockIdx.z;
    const size_t base = (size_t)b * Sdim * HD + (size_t)h * Ddim;

    // LDSM lane bases
    const uint32_t q_loff = (uint32_t)(rbase + (lane & 15)) * TROW + (uint32_t)((lane >> 4) << 4);
    const uint32_t b_loff = (uint32_t)((lane & 7) + ((lane >> 4) << 3)) * TROW
                          + (uint32_t)(((lane >> 3) & 1) << 4);
    const uint32_t v_loff = (uint32_t)((lane & 7) + (((lane >> 3) & 1) << 3)) * TROW
                          + (uint32_t)((lane >> 4) << 4);

    const int ntiles = (q0 >> 6) + 2;

    auto issue_kv = [&](int t) {
        const uint32_t kvb = kv_u32 + (uint32_t)(t % 3) * KVBUF;
        const int jr = t * 64;
        #pragma unroll
        for (int i = 0; i < 4; i++) {
            const int idx = tid + i * 256;
            const int j = idx & 7;
            if (idx < 512) {
                const int r = idx >> 3;
                cp16(kvb + r * TROW + j * 16u, K + base + (size_t)(jr + r) * HD + j * 8);
            } else {
                const int r = (idx - 512) >> 3;
                cp16(kvb + KVTILE_B + r * TROW + j * 16u,
                     V + base + (size_t)(jr + r) * HD + j * 8);
            }
        }
    };

    // prologue: G0 = Q(128 rows) + KV tile 0 ; G1 = KV tile 1 (always exists)
    #pragma unroll
    for (int i = 0; i < 4; i++) {
        const int idx = tid + i * 256;
        const int r = idx >> 3, j = idx & 7;
        cp16(q_u32 + r * TROW + j * 16u, Q + base + (size_t)(q0 + r) * HD + j * 8);
    }
    issue_kv(0);
    cp_commit();
    issue_kv(1);
    cp_commit();

    float m1 = -1e30f, m2 = -1e30f, l1 = 0.f, l2 = 0.f;
    float o[8][4] = {};
    const int grow_base = q0 + rbase;    // warp's first global query row
    const int grow1 = grow_base + g, grow2 = grow1 + 8;

    for (int jt = 0; jt < ntiles; jt++) {
        cp_wait<1>();
        __syncthreads();     // tile jt ready; all warps done with tile jt-1's buffer

        if (jt + 2 < ntiles) issue_kv(jt + 2);
        cp_commit();

        const int j0 = jt * 64;
        const uint32_t kb32 = kv_u32 + (uint32_t)(jt % 3) * KVBUF;
        const uint32_t vb32 = kb32 + KVTILE_B;
        const bool active = (j0 <= grow_base + 15);   // warp-uniform

        if (active) {
            // S = Q K^T (16 rows x 64 cols), log2 domain
            float s[8][4] = {};
            #pragma unroll
            for (int kb = 0; kb < 4; kb++) {
                uint32_t af[4];
                ldsm4(af, q_u32 + q_loff + kb * 32u);
                #pragma unroll
                for (int nb = 0; nb < 4; nb++) {
                    uint32_t bf[4];
                    ldsm4(bf, kb32 + b_loff + (uint32_t)(nb * 16) * TROW + kb * 32u);
                    mma_bf16(s[nb * 2],     af[0], af[1], af[2], af[3], bf[0], bf[1]);
                    mma_bf16(s[nb * 2 + 1], af[0], af[1], af[2], af[3], bf[2], bf[3]);
                }
            }

            // online softmax (base-2); p stored back into s
            const bool diag = (j0 + 63 > grow_base);
            float rm1 = -1e30f, rm2 = -1e30f;
            #pragma unroll
            for (int nt = 0; nt < 8; nt++) {
                if (diag) {
                    const int c0 = j0 + nt * 8 + 2 * tg;
                    if (c0     > grow1) s[nt][0] = -1e30f;
                    if (c0 + 1 > grow1) s[nt][1] = -1e30f;
                    if (c0     > grow2) s[nt][2] = -1e30f;
                    if (c0 + 1 > grow2) s[nt][3] = -1e30f;
                }
                rm1 = fmaxf(rm1, fmaxf(s[nt][0], s[nt][1]));
                rm2 = fmaxf(rm2, fmaxf(s[nt][2], s[nt][3]));
            }
            rm1 = fmaxf(rm1, __shfl_xor_sync(0xffffffffu, rm1, 1));
            rm1 = fmaxf(rm1, __shfl_xor_sync(0xffffffffu, rm1, 2));
            rm2 = fmaxf(rm2, __shfl_xor_sync(0xffffffffu, rm2, 1));
            rm2 = fmaxf(rm2, __shfl_xor_sync(0xffffffffu, rm2, 2));

            const float mn1 = fmaxf(m1, rm1), mn2 = fmaxf(m2, rm2);
            const float sc1 = ex2f(m1 - mn1), sc2 = ex2f(m2 - mn2);
            m1 = mn1; m2 = mn2;

            float sum1 = 0.f, sum2 = 0.f;
            #pragma unroll
            for (int nt = 0; nt < 8; nt++) {
                s[nt][0] = ex2f(s[nt][0] - mn1);
                s[nt][1] = ex2f(s[nt][1] - mn1);
                s[nt][2] = ex2f(s[nt][2] - mn2);
                s[nt][3] = ex2f(s[nt][3] - mn2);
                sum1 += s[nt][0] + s[nt][1];
                sum2 += s[nt][2] + s[nt][3];
            }
            sum1 += __shfl_xor_sync(0xffffffffu, sum1, 1);
            sum1 += __shfl_xor_sync(0xffffffffu, sum1, 2);
            sum2 += __shfl_xor_sync(0xffffffffu, sum2, 1);
            sum2 += __shfl_xor_sync(0xffffffffu, sum2, 2);
            l1 = l1 * sc1 + sum1;
            l2 = l2 * sc2 + sum2;

            #pragma unroll
            for (int nt = 0; nt < 8; nt++) {
                o[nt][0] *= sc1; o[nt][1] *= sc1;
                o[nt][2] *= sc2; o[nt][3] *= sc2;
            }

            // O += P V : P A-fragments built directly from S C-fragments
            #pragma unroll
            for (int kb = 0; kb < 4; kb++) {
                uint32_t pa[4];
                pa[0] = packbf(s[2 * kb][0],     s[2 * kb][1]);
                pa[1] = packbf(s[2 * kb][2],     s[2 * kb][3]);
                pa[2] = packbf(s[2 * kb + 1][0], s[2 * kb + 1][1]);
                pa[3] = packbf(s[2 * kb + 1][2], s[2 * kb + 1][3]);
                #pragma unroll
                for (int nb = 0; nb < 4; nb++) {
                    uint32_t bf[4];
                    ldsm4t(bf, vb32 + v_loff + (uint32_t)(kb * 16) * TROW + nb * 32u);
                    mma_bf16(o[nb * 2],     pa[0], pa[1], pa[2], pa[3], bf[0], bf[1]);
                    mma_bf16(o[nb * 2 + 1], pa[0], pa[1], pa[2], pa[3], bf[2], bf[3]);
                }
            }
        }
    }

    const float inv1 = 1.0f / l1;
    const float inv2 = 1.0f / l2;
    #pragma unroll
    for (int nt = 0; nt < 8; nt++) {
        const int cb = nt * 8 + 2 * tg;
        *reinterpret_cast<uint32_t*>(O + base + (size_t)grow1 * HD + cb) =
            packbf(o[nt][0] * inv1, o[nt][1] * inv1);
        *reinterpret_cast<uint32_t*>(O + base + (size_t)grow2 * HD + cb) =
            packbf(o[nt][2] * inv2, o[nt][3] * inv2);
    }
}

// ---------------- launch ----------------------------------------------------
extern "C" void kernel_launch(void* const* d_in, const int* in_sizes, int n_in,
                              void* d_out, int out_size) {
    const float* x     = (const float*)d_in[0];
    const float* gamma = (const float*)d_in[1];
    const float* beta  = (const float*)d_in[2];
    const float* Wq    = (const float*)d_in[3];
    const float* bq    = (const float*)d_in[4];
    const float* Wk    = (const float*)d_in[5];
    const float* bk    = (const float*)d_in[6];
    const float* Wv    = (const float*)d_in[7];
    const float* bv    = (const float*)d_in[8];
    const float* Wo    = (const float*)d_in[9];
    const float* bo    = (const float*)d_in[10];
    float* out = (float*)d_out;

    __nv_bfloat16 *xn, *qp, *kp, *vp, *ao, *wt;
    cudaGetSymbolAddress((void**)&xn, g_xn);
    cudaGetSymbolAddress((void**)&qp, g_q);
    cudaGetSymbolAddress((void**)&kp, g_k);
    cudaGetSymbolAddress((void**)&vp, g_v);
    cudaGetSymbolAddress((void**)&ao, g_ao);
    cudaGetSymbolAddress((void**)&wt, g_wt);

    prep_kernel<<<Mrows + 4096, 256>>>(x, gamma, beta, xn, Wq, Wk, Wv, Wo, wt);

    cudaFuncSetAttribute(qkv_gemm_kernel, cudaFuncAttributeMaxDynamicSharedMemorySize,
                         GEMM_SMEM_BYTES);
    cudaFuncSetAttribute(o_gemm_kernel, cudaFuncAttributeMaxDynamicSharedMemorySize,
                         GEMM_SMEM_BYTES);

    qkv_gemm_kernel<<<dim3(24, Mrows / 128), 256, GEMM_SMEM_BYTES>>>(
        xn, wt, bq, bk, bv, qp, kp, vp);

    cudaFuncSetAttribute(attn_bf16_kernel, cudaFuncAttributeMaxDynamicSharedMemorySize,
                         ATTN_SMEM_BYTES);
    attn_bf16_kernel<<<dim3(Sdim / 128, Hdim, Bdim), 256, ATTN_SMEM_BYTES>>>(qp, kp, vp, ao);

    o_gemm_kernel<<<dim3(8, Mrows / 128), 256, GEMM_SMEM_BYTES>>>(ao, wt, bo, x, out);
}

// round 15
// speedup vs baseline: 1.2239x; 1.0200x over previous
#include <cuda_runtime.h>
#include <cuda_bf16.h>
#include <math.h>
#include <stdint.h>

#define Bdim 4
#define Sdim 2048
#define Edim 1024
#define Hdim 16
#define Ddim 64
#define Mrows (Bdim * Sdim)          // 8192
#define HD (Hdim * Ddim)             // 1024
#define GK 1024

// ---------------- scratch (static device globals; no allocs) ----------------
__device__ __nv_bfloat16 g_xn[Mrows * Edim];
__device__ __nv_bfloat16 g_q [Mrows * HD];
__device__ __nv_bfloat16 g_k [Mrows * HD];
__device__ __nv_bfloat16 g_v [Mrows * HD];
__device__ __nv_bfloat16 g_ao[Mrows * HD];
__device__ __nv_bfloat16 g_wt[4 * GK * GK];   // transposed weights [N][K] bf16

// ---------------- helpers ----------------------------------------------------
__device__ __forceinline__ uint32_t packbf(float lo, float hi) {
    uint32_t d;
    asm("cvt.rn.bf16x2.f32 %0, %1, %2;" : "=r"(d) : "f"(hi), "f"(lo));
    return d;
}
__device__ __forceinline__ float ex2f(float x) {
    float y;
    asm("ex2.approx.f32 %0, %1;" : "=f"(y) : "f"(x));
    return y;
}

// D(16x8) += A(16x16,row) * B(16x8,col)  bf16 -> fp32
__device__ __forceinline__ void mma_bf16(float c[4],
                                         uint32_t a0, uint32_t a1, uint32_t a2, uint32_t a3,
                                         uint32_t b0, uint32_t b1) {
    asm volatile(
        "mma.sync.aligned.m16n8k16.row.col.f32.bf16.bf16.f32 "
        "{%0,%1,%2,%3}, {%4,%5,%6,%7}, {%8,%9}, {%0,%1,%2,%3};\n"
        : "+f"(c[0]), "+f"(c[1]), "+f"(c[2]), "+f"(c[3])
        : "r"(a0), "r"(a1), "r"(a2), "r"(a3), "r"(b0), "r"(b1));
}

__device__ __forceinline__ void ldsm4(uint32_t r[4], uint32_t addr) {
    asm volatile("ldmatrix.sync.aligned.m8n8.x4.shared.b16 {%0,%1,%2,%3}, [%4];"
                 : "=r"(r[0]), "=r"(r[1]), "=r"(r[2]), "=r"(r[3])
                 : "r"(addr));
}
__device__ __forceinline__ void ldsm4t(uint32_t r[4], uint32_t addr) {
    asm volatile("ldmatrix.sync.aligned.m8n8.x4.trans.shared.b16 {%0,%1,%2,%3}, [%4];"
                 : "=r"(r[0]), "=r"(r[1]), "=r"(r[2]), "=r"(r[3])
                 : "r"(addr));
}

__device__ __forceinline__ void cp16(uint32_t dst, const void* src) {
    asm volatile("cp.async.cg.shared.global [%0], [%1], 16;" :: "r"(dst), "l"(src));
}
__device__ __forceinline__ void cp_commit() {
    asm volatile("cp.async.commit_group;");
}
template <int N>
__device__ __forceinline__ void cp_wait() {
    asm volatile("cp.async.wait_group %0;" :: "n"(N));
}

// ---------------- merged prep: LayerNorm (blocks 0..8191) + transpose -------
__global__ void __launch_bounds__(256) prep_kernel(const float* __restrict__ x,
                                                   const float* __restrict__ gamma,
                                                   const float* __restrict__ beta,
                                                   __nv_bfloat16* __restrict__ y,
                                                   const float* __restrict__ Wq,
                                                   const float* __restrict__ Wk,
                                                   const float* __restrict__ Wv,
                                                   const float* __restrict__ Wo,
                                                   __nv_bfloat16* __restrict__ wt) {
    __shared__ float tsh[32][33];
    const int tid = threadIdx.x;

    if (blockIdx.x < Mrows) {
        const int row = blockIdx.x;
        const float4 xv = reinterpret_cast<const float4*>(x + (size_t)row * Edim)[tid];
        float s  = xv.x + xv.y + xv.z + xv.w;
        float ss = xv.x * xv.x + xv.y * xv.y + xv.z * xv.z + xv.w * xv.w;
        #pragma unroll
        for (int m = 16; m; m >>= 1) {
            s  += __shfl_xor_sync(0xffffffffu, s,  m);
            ss += __shfl_xor_sync(0xffffffffu, ss, m);
        }
        __shared__ float sh_s[8], sh_ss[8];
        __shared__ float s_mu, s_rstd;
        const int w = tid >> 5, l = tid & 31;
        if (l == 0) { sh_s[w] = s; sh_ss[w] = ss; }
        __syncthreads();
        if (w == 0) {
            float a = (l < 8) ? sh_s[l]  : 0.f;
            float c = (l < 8) ? sh_ss[l] : 0.f;
            #pragma unroll
            for (int m = 4; m; m >>= 1) {
                a += __shfl_xor_sync(0xffffffffu, a, m);
                c += __shfl_xor_sync(0xffffffffu, c, m);
            }
            if (l == 0) {
                float mu  = a * (1.0f / Edim);
                float var = c * (1.0f / Edim) - mu * mu;
                s_mu = mu;
                s_rstd = rsqrtf(var + 1e-5f);
            }
        }
        __syncthreads();
        const float mu = s_mu, rstd = s_rstd;
        const float4 gv = reinterpret_cast<const float4*>(gamma)[tid];
        const float4 bv = reinterpret_cast<const float4*>(beta)[tid];
        uint2 o2;
        o2.x = packbf((xv.x - mu) * rstd * gv.x + bv.x, (xv.y - mu) * rstd * gv.y + bv.y);
        o2.y = packbf((xv.z - mu) * rstd * gv.z + bv.z, (xv.w - mu) * rstd * gv.w + bv.w);
        *reinterpret_cast<uint2*>(y + (size_t)row * Edim + tid * 4) = o2;
    } else {
        const int bid = blockIdx.x - Mrows;
        const int z = bid >> 10;
        const int rem = bid & 1023;
        const int x0 = (rem & 31) << 5, y0 = (rem >> 5) << 5;
        const float* W = (z == 0) ? Wq : (z == 1) ? Wk : (z == 2) ? Wv : Wo;
        __nv_bfloat16* T = wt + (size_t)z * GK * GK;
        const int tx = tid & 31, ty = tid >> 5;   // 32x8
        #pragma unroll
        for (int i = 0; i < 32; i += 8)
            tsh[ty + i][tx] = W[(size_t)(y0 + ty + i) * GK + x0 + tx];
        __syncthreads();
        #pragma unroll
        for (int i = 0; i < 32; i += 8)
            T[(size_t)(x0 + ty + i) * GK + y0 + tx] = __float2bfloat16(tsh[tx][ty + i]);
    }
}

// ---------------- bf16 GEMM: 128x128 tile, BK=64, 3-stage cp.async ----------
#define BK 64
#define ROWB 144u
#define STG_A 0u
#define STG_B 18432u
#define STAGE_BYTES 36864u
#define GSTAGES 3
#define GEMM_SMEM_BYTES (GSTAGES * STAGE_BYTES)   // 110592

template <bool BF16OUT>
__device__ __forceinline__ void gemm_body(const __nv_bfloat16* __restrict__ A,
                                          const __nv_bfloat16* __restrict__ WT,
                                          const float* __restrict__ bias,
                                          const float* __restrict__ res,
                                          void* __restrict__ C,
                                          int bx, int by, float oscale) {
    extern __shared__ __align__(16) char smem[];
    const uint32_t s0 = (uint32_t)__cvta_generic_to_shared(smem);

    const int tid  = threadIdx.x;
    const int lane = tid & 31;
    const int wid  = tid >> 5;
    const int g  = lane >> 2;
    const int tg = lane & 3;
    const int wm = wid >> 2;
    const int wn = wid & 3;
    const int row0 = by * 128;
    const int col0 = bx * 128;
    const int N = 1024;

    const uint32_t a_off = STG_A + (uint32_t)(wm * 64 + (lane & 15)) * ROWB
                                 + (uint32_t)((lane >> 4) << 4);
    const uint32_t b_off = STG_B + (uint32_t)(wn * 32 + (lane & 7) + ((lane >> 4) << 3)) * ROWB
                                 + (uint32_t)(((lane >> 3) & 1) << 4);

    auto issue_tile = [&](int t) {
        const uint32_t sb = s0 + (uint32_t)(t % GSTAGES) * STAGE_BYTES;
        const int gk = t * BK;
        #pragma unroll
        for (int i = 0; i < 8; i++) {
            const int idx = tid + i * 256;
            const int r = (idx >> 3) & 127;
            const int j = idx & 7;
            if (idx < 1024)
                cp16(sb + STG_A + r * ROWB + j * 16u,
                     A + (size_t)(row0 + r) * GK + gk + j * 8);
            else
                cp16(sb + STG_B + r * ROWB + j * 16u,
                     WT + (size_t)(col0 + r) * GK + gk + j * 8);
        }
        cp_commit();
    };

    issue_tile(0);
    issue_tile(1);

    float acc[4][4][4] = {};
    const int NIT = GK / BK;     // 16

    for (int it = 0; it < NIT; it++) {
        cp_wait<GSTAGES - 2>();
        __syncthreads();

        if (it + GSTAGES - 1 < NIT) issue_tile(it + GSTAGES - 1);
        else cp_commit();

        const uint32_t sb = s0 + (uint32_t)(it % GSTAGES) * STAGE_BYTES;
        #pragma unroll
        for (int kb = 0; kb < 4; kb++) {
            uint32_t af[4][4], bf[2][4];
            #pragma unroll
            for (int mi = 0; mi < 4; mi++)
                ldsm4(af[mi], sb + a_off + (uint32_t)(mi * 16) * ROWB + kb * 32u);
            #pragma unroll
            for (int nb = 0; nb < 2; nb++)
                ldsm4(bf[nb], sb + b_off + (uint32_t)(nb * 16) * ROWB + kb * 32u);
            #pragma unroll
            for (int mi = 0; mi < 4; mi++)
                #pragma unroll
                for (int nb = 0; nb < 2; nb++) {
                    mma_bf16(acc[mi][nb * 2],     af[mi][0], af[mi][1], af[mi][2], af[mi][3],
                             bf[nb][0], bf[nb][1]);
                    mma_bf16(acc[mi][nb * 2 + 1], af[mi][0], af[mi][1], af[mi][2], af[mi][3],
                             bf[nb][2], bf[nb][3]);
                }
        }
    }

    #pragma unroll
    for (int mi = 0; mi < 4; mi++) {
        const int r1 = row0 + wm * 64 + mi * 16 + g;
        const int r2 = r1 + 8;
        #pragma unroll
        for (int ni = 0; ni < 4; ni++) {
            const int cb = col0 + wn * 32 + ni * 8 + 2 * tg;
            float v0 = (acc[mi][ni][0] + bias[cb])     * oscale;
            float v1 = (acc[mi][ni][1] + bias[cb + 1]) * oscale;
            float v2 = (acc[mi][ni][2] + bias[cb])     * oscale;
            float v3 = (acc[mi][ni][3] + bias[cb + 1]) * oscale;
            if (BF16OUT) {
                ((uint32_t*)C)[(size_t)r1 * (N / 2) + (cb >> 1)] = packbf(v0, v1);
                ((uint32_t*)C)[(size_t)r2 * (N / 2) + (cb >> 1)] = packbf(v2, v3);
            } else {
                const float2 r1v = *reinterpret_cast<const float2*>(res + (size_t)r1 * N + cb);
                const float2 r2v = *reinterpret_cast<const float2*>(res + (size_t)r2 * N + cb);
                float2 w1; w1.x = v0 + r1v.x; w1.y = v1 + r1v.y;
                float2 w2; w2.x = v2 + r2v.x; w2.y = v3 + r2v.y;
                *reinterpret_cast<float2*>((float*)C + (size_t)r1 * N + cb) = w1;
                *reinterpret_cast<float2*>((float*)C + (size_t)r2 * N + cb) = w2;
            }
        }
    }
}

__global__ void __launch_bounds__(256, 2) qkv_gemm_kernel(const __nv_bfloat16* __restrict__ A,
                                                          const __nv_bfloat16* __restrict__ wt,
                                                          const float* __restrict__ bq,
                                                          const float* __restrict__ bk,
                                                          const float* __restrict__ bv,
                                                          __nv_bfloat16* __restrict__ Cq,
                                                          __nv_bfloat16* __restrict__ Ck,
                                                          __nv_bfloat16* __restrict__ Cv) {
    const int mat = blockIdx.x >> 3;
    const int bx  = blockIdx.x & 7;
    const __nv_bfloat16* WT = wt + (size_t)mat * GK * GK;
    const float* bias = (mat == 0) ? bq : (mat == 1) ? bk : bv;
    __nv_bfloat16* C  = (mat == 0) ? Cq : (mat == 1) ? Ck : Cv;
    const float sc = (mat == 0) ? 0.1803368801111354f : 1.0f;   // 0.125 * log2(e)
    gemm_body<true>(A, WT, bias, nullptr, C, bx, blockIdx.y, sc);
}

__global__ void __launch_bounds__(256, 2) o_gemm_kernel(const __nv_bfloat16* __restrict__ A,
                                                        const __nv_bfloat16* __restrict__ wt,
                                                        const float* __restrict__ bo,
                                                        const float* __restrict__ res,
                                                        float* __restrict__ out) {
    gemm_body<false>(A, wt + (size_t)3 * GK * GK, bo, res, out, blockIdx.x, blockIdx.y, 1.0f);
}

// ---------------- Flash attention (causal), bf16, Q-in-registers ------------
// grid (S/128, H, B), 256 threads (8 warps). Warp w owns 16 query rows.
// Q fragments held in registers (loaded once). KV in 128-key tiles,
// 3-deep ring => ONE __syncthreads per 128 keys. log2-domain softmax.
#define TROW 144u
#define KVTILE_B (128u * TROW)           // 18432 (K part; V same)
#define KVBUF (2u * KVTILE_B)            // 36864 per ring slot
#define ATTN_SMEM_BYTES (3 * KVBUF)      // 110592

__global__ void __launch_bounds__(256, 2) attn_bf16_kernel(const __nv_bfloat16* __restrict__ Q,
                                                           const __nv_bfloat16* __restrict__ K,
                                                           const __nv_bfloat16* __restrict__ V,
                                                           __nv_bfloat16* __restrict__ O) {
    extern __shared__ __align__(16) char sm[];
    const uint32_t kv_u32 = (uint32_t)__cvta_generic_to_shared(sm);

    const int tid  = threadIdx.x;
    const int lane = tid & 31;
    const int wid  = tid >> 5;           // 0..7
    const int g  = lane >> 2;
    const int tg = lane & 3;
    const int rbase = wid * 16;
    const int qblk = (int)gridDim.x - 1 - (int)blockIdx.x;   // LPT: heavy CTAs first
    const int q0 = qblk * 128;
    const int h = blockIdx.y, b = blockIdx.z;
    const size_t base = (size_t)b * Sdim * HD + (size_t)h * Ddim;

    // LDSM lane bases
    const uint32_t q_loff = (uint32_t)(rbase + (lane & 15)) * TROW + (uint32_t)((lane >> 4) << 4);
    const uint32_t b_loff = (uint32_t)((lane & 7) + ((lane >> 4) << 3)) * TROW
                          + (uint32_t)(((lane >> 3) & 1) << 4);
    const uint32_t v_loff = (uint32_t)((lane & 7) + (((lane >> 3) & 1) << 3)) * TROW
                          + (uint32_t)((lane >> 4) << 4);

    const int ktiles = qblk + 1;          // 128-key tiles

    // KV tile loader: 128 K rows + 128 V rows into ring slot t%3
    auto issue_kv = [&](int t) {
        const uint32_t kvb = kv_u32 + (uint32_t)(t % 3) * KVBUF;
        const int jr = t * 128;
        #pragma unroll
        for (int i = 0; i < 8; i++) {
            const int idx = tid + i * 256;
            const int j = idx & 7;
            if (idx < 1024) {
                const int r = idx >> 3;
                cp16(kvb + r * TROW + j * 16u, K + base + (size_t)(jr + r) * HD + j * 8);
            } else {
                const int r = (idx - 1024) >> 3;
                cp16(kvb + KVTILE_B + r * TROW + j * 16u,
                     V + base + (size_t)(jr + r) * HD + j * 8);
            }
        }
        cp_commit();
    };

    // ---- prologue: stage Q into ring slot 2, load fragments to registers ---
    {
        const uint32_t qstage = kv_u32 + 2u * KVBUF;
        #pragma unroll
        for (int i = 0; i < 4; i++) {
            const int idx = tid + i * 256;
            const int r = idx >> 3, j = idx & 7;
            cp16(qstage + r * TROW + j * 16u, Q + base + (size_t)(q0 + r) * HD + j * 8);
        }
        cp_commit();
        cp_wait<0>();
        __syncthreads();
    }
    uint32_t qf[4][4];
    {
        const uint32_t qstage = kv_u32 + 2u * KVBUF;
        #pragma unroll
        for (int kb = 0; kb < 4; kb++)
            ldsm4(qf[kb], qstage + q_loff + kb * 32u);
    }
    __syncthreads();   // all warps done reading Q staging before slot 2 is refilled

    issue_kv(0);
    if (ktiles > 1) issue_kv(1);
    else cp_commit();

    float m1 = -1e30f, m2 = -1e30f, l1 = 0.f, l2 = 0.f;
    float o[8][4] = {};
    const int grow_base = q0 + rbase;
    const int grow1 = grow_base + g, grow2 = grow1 + 8;

    for (int jt = 0; jt < ktiles; jt++) {
        cp_wait<1>();
        __syncthreads();     // tile jt ready; all warps done with slot (jt+1)%3

        if (jt + 2 < ktiles) issue_kv(jt + 2);
        else cp_commit();

        const uint32_t kt32 = kv_u32 + (uint32_t)(jt % 3) * KVBUF;
        const uint32_t vt32 = kt32 + KVTILE_B;

        #pragma unroll
        for (int sub = 0; sub < 2; sub++) {
            const int j0 = jt * 128 + sub * 64;
            if (j0 > grow_base + 15) break;    // warp-uniform causal skip
            const uint32_t kb32 = kt32 + (uint32_t)(sub * 64) * TROW;
            const uint32_t vb32 = vt32 + (uint32_t)(sub * 64) * TROW;

            // S = Q K^T (16 rows x 64 cols), log2 domain
            float s[8][4] = {};
            #pragma unroll
            for (int kb = 0; kb < 4; kb++) {
                #pragma unroll
                for (int nb = 0; nb < 4; nb++) {
                    uint32_t bf[4];
                    ldsm4(bf, kb32 + b_loff + (uint32_t)(nb * 16) * TROW + kb * 32u);
                    mma_bf16(s[nb * 2],     qf[kb][0], qf[kb][1], qf[kb][2], qf[kb][3],
                             bf[0], bf[1]);
                    mma_bf16(s[nb * 2 + 1], qf[kb][0], qf[kb][1], qf[kb][2], qf[kb][3],
                             bf[2], bf[3]);
                }
            }

            // online softmax (base-2); p stored back into s
            const bool diag = (j0 + 63 > grow_base);
            float rm1 = -1e30f, rm2 = -1e30f;
            #pragma unroll
            for (int nt = 0; nt < 8; nt++) {
                if (diag) {
                    const int c0 = j0 + nt * 8 + 2 * tg;
                    if (c0     > grow1) s[nt][0] = -1e30f;
                    if (c0 + 1 > grow1) s[nt][1] = -1e30f;
                    if (c0     > grow2) s[nt][2] = -1e30f;
                    if (c0 + 1 > grow2) s[nt][3] = -1e30f;
                }
                rm1 = fmaxf(rm1, fmaxf(s[nt][0], s[nt][1]));
                rm2 = fmaxf(rm2, fmaxf(s[nt][2], s[nt][3]));
            }
            rm1 = fmaxf(rm1, __shfl_xor_sync(0xffffffffu, rm1, 1));
            rm1 = fmaxf(rm1, __shfl_xor_sync(0xffffffffu, rm1, 2));
            rm2 = fmaxf(rm2, __shfl_xor_sync(0xffffffffu, rm2, 1));
            rm2 = fmaxf(rm2, __shfl_xor_sync(0xffffffffu, rm2, 2));

            const float mn1 = fmaxf(m1, rm1), mn2 = fmaxf(m2, rm2);
            const float sc1 = ex2f(m1 - mn1), sc2 = ex2f(m2 - mn2);
            m1 = mn1; m2 = mn2;

            float sum1 = 0.f, sum2 = 0.f;
            #pragma unroll
            for (int nt = 0; nt < 8; nt++) {
                s[nt][0] = ex2f(s[nt][0] - mn1);
                s[nt][1] = ex2f(s[nt][1] - mn1);
                s[nt][2] = ex2f(s[nt][2] - mn2);
                s[nt][3] = ex2f(s[nt][3] - mn2);
                sum1 += s[nt][0] + s[nt][1];
                sum2 += s[nt][2] + s[nt][3];
            }
            sum1 += __shfl_xor_sync(0xffffffffu, sum1, 1);
            sum1 += __shfl_xor_sync(0xffffffffu, sum1, 2);
            sum2 += __shfl_xor_sync(0xffffffffu, sum2, 1);
            sum2 += __shfl_xor_sync(0xffffffffu, sum2, 2);
            l1 = l1 * sc1 + sum1;
            l2 = l2 * sc2 + sum2;

            #pragma unroll
            for (int nt = 0; nt < 8; nt++) {
                o[nt][0] *= sc1; o[nt][1] *= sc1;
                o[nt][2] *= sc2; o[nt][3] *= sc2;
            }

            // O += P V : P A-fragments built directly from S C-fragments
            #pragma unroll
            for (int kb = 0; kb < 4; kb++) {
                uint32_t pa[4];
                pa[0] = packbf(s[2 * kb][0],     s[2 * kb][1]);
                pa[1] = packbf(s[2 * kb][2],     s[2 * kb][3]);
                pa[2] = packbf(s[2 * kb + 1][0], s[2 * kb + 1][1]);
                pa[3] = packbf(s[2 * kb + 1][2], s[2 * kb + 1][3]);
                #pragma unroll
                for (int nb = 0; nb < 4; nb++) {
                    uint32_t bf[4];
                    ldsm4t(bf, vb32 + v_loff + (uint32_t)(kb * 16) * TROW + nb * 32u);
                    mma_bf16(o[nb * 2],     pa[0], pa[1], pa[2], pa[3], bf[0], bf[1]);
                    mma_bf16(o[nb * 2 + 1], pa[0], pa[1], pa[2], pa[3], bf[2], bf[3]);
                }
            }
        }
    }

    const float inv1 = 1.0f / l1;
    const float inv2 = 1.0f / l2;
    #pragma unroll
    for (int nt = 0; nt < 8; nt++) {
        const int cb = nt * 8 + 2 * tg;
        *reinterpret_cast<uint32_t*>(O + base + (size_t)grow1 * HD + cb) =
            packbf(o[nt][0] * inv1, o[nt][1] * inv1);
        *reinterpret_cast<uint32_t*>(O + base + (size_t)grow2 * HD + cb) =
            packbf(o[nt][2] * inv2, o[nt][3] * inv2);
    }
}

// ---------------- launch ----------------------------------------------------
extern "C" void kernel_launch(void* const* d_in, const int* in_sizes, int n_in,
                              void* d_out, int out_size) {
    const float* x     = (const float*)d_in[0];
    const float* gamma = (const float*)d_in[1];
    const float* beta  = (const float*)d_in[2];
    const float* Wq    = (const float*)d_in[3];
    const float* bq    = (const float*)d_in[4];
    const float* Wk    = (const float*)d_in[5];
    const float* bk    = (const float*)d_in[6];
    const float* Wv    = (const float*)d_in[7];
    const float* bv    = (const float*)d_in[8];
    const float* Wo    = (const float*)d_in[9];
    const float* bo    = (const float*)d_in[10];
    float* out = (float*)d_out;

    __nv_bfloat16 *xn, *qp, *kp, *vp, *ao, *wt;
    cudaGetSymbolAddress((void**)&xn, g_xn);
    cudaGetSymbolAddress((void**)&qp, g_q);
    cudaGetSymbolAddress((void**)&kp, g_k);
    cudaGetSymbolAddress((void**)&vp, g_v);
    cudaGetSymbolAddress((void**)&ao, g_ao);
    cudaGetSymbolAddress((void**)&wt, g_wt);

    prep_kernel<<<Mrows + 4096, 256>>>(x, gamma, beta, xn, Wq, Wk, Wv, Wo, wt);

    cudaFuncSetAttribute(qkv_gemm_kernel, cudaFuncAttributeMaxDynamicSharedMemorySize,
                         GEMM_SMEM_BYTES);
    cudaFuncSetAttribute(o_gemm_kernel, cudaFuncAttributeMaxDynamicSharedMemorySize,
                         GEMM_SMEM_BYTES);

    qkv_gemm_kernel<<<dim3(24, Mrows / 128), 256, GEMM_SMEM_BYTES>>>(
        xn, wt, bq, bk, bv, qp, kp, vp);

    cudaFuncSetAttribute(attn_bf16_kernel, cudaFuncAttributeMaxDynamicSharedMemorySize,
                         ATTN_SMEM_BYTES);
    attn_bf16_kernel<<<dim3(Sdim / 128, Hdim, Bdim), 256, ATTN_SMEM_BYTES>>>(qp, kp, vp, ao);

    o_gemm_kernel<<<dim3(8, Mrows / 128), 256, GEMM_SMEM_BYTES>>>(ao, wt, bo, x, out);
}

// round 16
// speedup vs baseline: 1.2283x; 1.0036x over previous
#include <cuda_runtime.h>
#include <cuda_bf16.h>
#include <math.h>
#include <stdint.h>

#define Bdim 4
#define Sdim 2048
#define Edim 1024
#define Hdim 16
#define Ddim 64
#define Mrows (Bdim * Sdim)          // 8192
#define HD (Hdim * Ddim)             // 1024
#define GK 1024

// ---------------- scratch (static device globals; no allocs) ----------------
__device__ __nv_bfloat16 g_xn[Mrows * Edim];
__device__ __nv_bfloat16 g_q [Mrows * HD];
__device__ __nv_bfloat16 g_k [Mrows * HD];
__device__ __nv_bfloat16 g_v [Mrows * HD];
__device__ __nv_bfloat16 g_ao[Mrows * HD];
__device__ __nv_bfloat16 g_wb[4 * GK * GK];   // bf16 weights, K-major [z][k][n]

// ---------------- helpers ----------------------------------------------------
__device__ __forceinline__ uint32_t packbf(float lo, float hi) {
    uint32_t d;
    asm("cvt.rn.bf16x2.f32 %0, %1, %2;" : "=r"(d) : "f"(hi), "f"(lo));
    return d;
}
__device__ __forceinline__ float ex2f(float x) {
    float y;
    asm("ex2.approx.f32 %0, %1;" : "=f"(y) : "f"(x));
    return y;
}

// D(16x8) += A(16x16,row) * B(16x8,col)  bf16 -> fp32
__device__ __forceinline__ void mma_bf16(float c[4],
                                         uint32_t a0, uint32_t a1, uint32_t a2, uint32_t a3,
                                         uint32_t b0, uint32_t b1) {
    asm volatile(
        "mma.sync.aligned.m16n8k16.row.col.f32.bf16.bf16.f32 "
        "{%0,%1,%2,%3}, {%4,%5,%6,%7}, {%8,%9}, {%0,%1,%2,%3};\n"
        : "+f"(c[0]), "+f"(c[1]), "+f"(c[2]), "+f"(c[3])
        : "r"(a0), "r"(a1), "r"(a2), "r"(a3), "r"(b0), "r"(b1));
}

__device__ __forceinline__ void ldsm4(uint32_t r[4], uint32_t addr) {
    asm volatile("ldmatrix.sync.aligned.m8n8.x4.shared.b16 {%0,%1,%2,%3}, [%4];"
                 : "=r"(r[0]), "=r"(r[1]), "=r"(r[2]), "=r"(r[3])
                 : "r"(addr));
}
__device__ __forceinline__ void ldsm4t(uint32_t r[4], uint32_t addr) {
    asm volatile("ldmatrix.sync.aligned.m8n8.x4.trans.shared.b16 {%0,%1,%2,%3}, [%4];"
                 : "=r"(r[0]), "=r"(r[1]), "=r"(r[2]), "=r"(r[3])
                 : "r"(addr));
}

__device__ __forceinline__ void cp16(uint32_t dst, const void* src) {
    asm volatile("cp.async.cg.shared.global [%0], [%1], 16;" :: "r"(dst), "l"(src));
}
__device__ __forceinline__ void cp_commit() {
    asm volatile("cp.async.commit_group;");
}
template <int N>
__device__ __forceinline__ void cp_wait() {
    asm volatile("cp.async.wait_group %0;" :: "n"(N));
}

// ---------------- merged prep: LayerNorm + streaming weight convert ---------
// LN blocks 0..8191; convert blocks 8192..12287 (fp32 [K][N] -> bf16 [K][N]).
__global__ void __launch_bounds__(256) prep_kernel(const float* __restrict__ x,
                                                   const float* __restrict__ gamma,
                                                   const float* __restrict__ beta,
                                                   __nv_bfloat16* __restrict__ y,
                                                   const float* __restrict__ Wq,
                                                   const float* __restrict__ Wk,
                                                   const float* __restrict__ Wv,
                                                   const float* __restrict__ Wo,
                                                   __nv_bfloat16* __restrict__ wb) {
    const int tid = threadIdx.x;

    if (blockIdx.x < Mrows) {
        const int row = blockIdx.x;
        const float4 xv = reinterpret_cast<const float4*>(x + (size_t)row * Edim)[tid];
        float s  = xv.x + xv.y + xv.z + xv.w;
        float ss = xv.x * xv.x + xv.y * xv.y + xv.z * xv.z + xv.w * xv.w;
        #pragma unroll
        for (int m = 16; m; m >>= 1) {
            s  += __shfl_xor_sync(0xffffffffu, s,  m);
            ss += __shfl_xor_sync(0xffffffffu, ss, m);
        }
        __shared__ float sh_s[8], sh_ss[8];
        __shared__ float s_mu, s_rstd;
        const int w = tid >> 5, l = tid & 31;
        if (l == 0) { sh_s[w] = s; sh_ss[w] = ss; }
        __syncthreads();
        if (w == 0) {
            float a = (l < 8) ? sh_s[l]  : 0.f;
            float c = (l < 8) ? sh_ss[l] : 0.f;
            #pragma unroll
            for (int m = 4; m; m >>= 1) {
                a += __shfl_xor_sync(0xffffffffu, a, m);
                c += __shfl_xor_sync(0xffffffffu, c, m);
            }
            if (l == 0) {
                float mu  = a * (1.0f / Edim);
                float var = c * (1.0f / Edim) - mu * mu;
                s_mu = mu;
                s_rstd = rsqrtf(var + 1e-5f);
            }
        }
        __syncthreads();
        const float mu = s_mu, rstd = s_rstd;
        const float4 gv = reinterpret_cast<const float4*>(gamma)[tid];
        const float4 bv = reinterpret_cast<const float4*>(beta)[tid];
        uint2 o2;
        o2.x = packbf((xv.x - mu) * rstd * gv.x + bv.x, (xv.y - mu) * rstd * gv.y + bv.y);
        o2.y = packbf((xv.z - mu) * rstd * gv.z + bv.z, (xv.w - mu) * rstd * gv.w + bv.w);
        *reinterpret_cast<uint2*>(y + (size_t)row * Edim + tid * 4) = o2;
    } else {
        // streaming fp32 -> bf16 convert (no transpose)
        const int bid = blockIdx.x - Mrows;         // 0..4095
        const int z = bid >> 10;
        const float* W = (z == 0) ? Wq : (z == 1) ? Wk : (z == 2) ? Wv : Wo;
        const size_t off = (size_t)(bid & 1023) * 1024 + tid * 4;
        const float4 wv = *reinterpret_cast<const float4*>(W + off);
        uint2 o2;
        o2.x = packbf(wv.x, wv.y);
        o2.y = packbf(wv.z, wv.w);
        *reinterpret_cast<uint2*>(wb + (size_t)z * GK * GK + off) = o2;
    }
}

// ---------------- bf16 GEMM: 128x128 tile, BK=64, 3-stage cp.async ----------
// A [M,K] row-major (A-fragments via ldsm4). W bf16 [K,N] row-major
// (B-fragments via ldsm4t, same pattern as the attention PV path).
#define BK 64
#define AROW 144u                          // 128B data + 16B pad
#define BROW 272u                          // 256B data + 16B pad
#define STG_A 0u
#define STG_B 18432u                       // 128 rows * 144B
#define STAGE_BYTES 35840u                 // + 64 rows * 272B
#define GSTAGES 3
#define GEMM_SMEM_BYTES (GSTAGES * STAGE_BYTES)   // 107520

template <bool BF16OUT>
__device__ __forceinline__ void gemm_body(const __nv_bfloat16* __restrict__ A,
                                          const __nv_bfloat16* __restrict__ W,
                                          const float* __restrict__ bias,
                                          const float* __restrict__ res,
                                          void* __restrict__ C,
                                          int bx, int by, float oscale) {
    extern __shared__ __align__(16) char smem[];
    const uint32_t s0 = (uint32_t)__cvta_generic_to_shared(smem);

    const int tid  = threadIdx.x;
    const int lane = tid & 31;
    const int wid  = tid >> 5;
    const int g  = lane >> 2;
    const int tg = lane & 3;
    const int wm = wid >> 2;
    const int wn = wid & 3;
    const int row0 = by * 128;
    const int col0 = bx * 128;
    const int N = 1024;

    const uint32_t a_off = STG_A + (uint32_t)(wm * 64 + (lane & 15)) * AROW
                                 + (uint32_t)((lane >> 4) << 4);
    // trans-B lane base (identical role to attention's v_loff), plus warp col offset
    const uint32_t b_off = STG_B + (uint32_t)((lane & 7) + (((lane >> 3) & 1) << 3)) * BROW
                                 + (uint32_t)((lane >> 4) << 4)
                                 + (uint32_t)(wn * 64);

    auto issue_tile = [&](int t) {
        const uint32_t sb = s0 + (uint32_t)(t % GSTAGES) * STAGE_BYTES;
        const int gk = t * BK;
        #pragma unroll
        for (int i = 0; i < 8; i++) {
            const int idx = tid + i * 256;       // 0..2047
            if (idx < 1024) {                    // A: 128 rows x 8 chunks
                const int r = idx >> 3, j = idx & 7;
                cp16(sb + STG_A + r * AROW + j * 16u,
                     A + (size_t)(row0 + r) * GK + gk + j * 8);
            } else {                             // B: 64 rows x 16 chunks
                const int loc = idx - 1024;
                const int r = loc >> 4, j = loc & 15;
                cp16(sb + STG_B + r * BROW + j * 16u,
                     W + (size_t)(gk + r) * N + col0 + j * 8);
            }
        }
        cp_commit();
    };

    issue_tile(0);
    issue_tile(1);

    float acc[4][4][4] = {};
    const int NIT = GK / BK;     // 16

    for (int it = 0; it < NIT; it++) {
        cp_wait<GSTAGES - 2>();
        __syncthreads();

        if (it + GSTAGES - 1 < NIT) issue_tile(it + GSTAGES - 1);
        else cp_commit();

        const uint32_t sb = s0 + (uint32_t)(it % GSTAGES) * STAGE_BYTES;
        #pragma unroll
        for (int kb = 0; kb < 4; kb++) {
            uint32_t af[4][4], bf[2][4];
            #pragma unroll
            for (int mi = 0; mi < 4; mi++)
                ldsm4(af[mi], sb + a_off + (uint32_t)(mi * 16) * AROW + kb * 32u);
            #pragma unroll
            for (int nb = 0; nb < 2; nb++)
                ldsm4t(bf[nb], sb + b_off + (uint32_t)(kb * 16) * BROW + nb * 32u);
            #pragma unroll
            for (int mi = 0; mi < 4; mi++)
                #pragma unroll
                for (int nb = 0; nb < 2; nb++) {
                    mma_bf16(acc[mi][nb * 2],     af[mi][0], af[mi][1], af[mi][2], af[mi][3],
                             bf[nb][0], bf[nb][1]);
                    mma_bf16(acc[mi][nb * 2 + 1], af[mi][0], af[mi][1], af[mi][2], af[mi][3],
                             bf[nb][2], bf[nb][3]);
                }
        }
    }

    #pragma unroll
    for (int mi = 0; mi < 4; mi++) {
        const int r1 = row0 + wm * 64 + mi * 16 + g;
        const int r2 = r1 + 8;
        #pragma unroll
        for (int ni = 0; ni < 4; ni++) {
            const int cb = col0 + wn * 32 + ni * 8 + 2 * tg;
            float v0 = (acc[mi][ni][0] + bias[cb])     * oscale;
            float v1 = (acc[mi][ni][1] + bias[cb + 1]) * oscale;
            float v2 = (acc[mi][ni][2] + bias[cb])     * oscale;
            float v3 = (acc[mi][ni][3] + bias[cb + 1]) * oscale;
            if (BF16OUT) {
                ((uint32_t*)C)[(size_t)r1 * (N / 2) + (cb >> 1)] = packbf(v0, v1);
                ((uint32_t*)C)[(size_t)r2 * (N / 2) + (cb >> 1)] = packbf(v2, v3);
            } else {
                const float2 r1v = *reinterpret_cast<const float2*>(res + (size_t)r1 * N + cb);
                const float2 r2v = *reinterpret_cast<const float2*>(res + (size_t)r2 * N + cb);
                float2 w1; w1.x = v0 + r1v.x; w1.y = v1 + r1v.y;
                float2 w2; w2.x = v2 + r2v.x; w2.y = v3 + r2v.y;
                *reinterpret_cast<float2*>((float*)C + (size_t)r1 * N + cb) = w1;
                *reinterpret_cast<float2*>((float*)C + (size_t)r2 * N + cb) = w2;
            }
        }
    }
}

__global__ void __launch_bounds__(256, 2) qkv_gemm_kernel(const __nv_bfloat16* __restrict__ A,
                                                          const __nv_bfloat16* __restrict__ wb,
                                                          const float* __restrict__ bq,
                                                          const float* __restrict__ bk,
                                                          const float* __restrict__ bv,
                                                          __nv_bfloat16* __restrict__ Cq,
                                                          __nv_bfloat16* __restrict__ Ck,
                                                          __nv_bfloat16* __restrict__ Cv) {
    const int mat = blockIdx.x >> 3;
    const int bx  = blockIdx.x & 7;
    const __nv_bfloat16* W = wb + (size_t)mat * GK * GK;
    const float* bias = (mat == 0) ? bq : (mat == 1) ? bk : bv;
    __nv_bfloat16* C  = (mat == 0) ? Cq : (mat == 1) ? Ck : Cv;
    const float sc = (mat == 0) ? 0.1803368801111354f : 1.0f;   // 0.125 * log2(e)
    gemm_body<true>(A, W, bias, nullptr, C, bx, blockIdx.y, sc);
}

__global__ void __launch_bounds__(256, 2) o_gemm_kernel(const __nv_bfloat16* __restrict__ A,
                                                        const __nv_bfloat16* __restrict__ wb,
                                                        const float* __restrict__ bo,
                                                        const float* __restrict__ res,
                                                        float* __restrict__ out) {
    gemm_body<false>(A, wb + (size_t)3 * GK * GK, bo, res, out, blockIdx.x, blockIdx.y, 1.0f);
}

// ---------------- Flash attention (causal), bf16, Q-in-registers ------------
// grid (S/128, H, B), 256 threads (8 warps). Warp w owns 16 query rows.
// Q fragments in registers; KV 128-key tiles, 3-deep ring; log2-domain softmax.
#define TROW 144u
#define KVTILE_B (128u * TROW)           // 18432 (K part; V same)
#define KVBUF (2u * KVTILE_B)            // 36864 per ring slot
#define ATTN_SMEM_BYTES (3 * KVBUF)      // 110592

__global__ void __launch_bounds__(256, 2) attn_bf16_kernel(const __nv_bfloat16* __restrict__ Q,
                                                           const __nv_bfloat16* __restrict__ K,
                                                           const __nv_bfloat16* __restrict__ V,
                                                           __nv_bfloat16* __restrict__ O) {
    extern __shared__ __align__(16) char sm[];
    const uint32_t kv_u32 = (uint32_t)__cvta_generic_to_shared(sm);

    const int tid  = threadIdx.x;
    const int lane = tid & 31;
    const int wid  = tid >> 5;
    const int g  = lane >> 2;
    const int tg = lane & 3;
    const int rbase = wid * 16;
    const int qblk = (int)gridDim.x - 1 - (int)blockIdx.x;   // LPT
    const int q0 = qblk * 128;
    const int h = blockIdx.y, b = blockIdx.z;
    const size_t base = (size_t)b * Sdim * HD + (size_t)h * Ddim;

    const uint32_t q_loff = (uint32_t)(rbase + (lane & 15)) * TROW + (uint32_t)((lane >> 4) << 4);
    const uint32_t b_loff = (uint32_t)((lane & 7) + ((lane >> 4) << 3)) * TROW
                          + (uint32_t)(((lane >> 3) & 1) << 4);
    const uint32_t v_loff = (uint32_t)((lane & 7) + (((lane >> 3) & 1) << 3)) * TROW
                          + (uint32_t)((lane >> 4) << 4);

    const int ktiles = qblk + 1;

    auto issue_kv = [&](int t) {
        const uint32_t kvb = kv_u32 + (uint32_t)(t % 3) * KVBUF;
        const int jr = t * 128;
        #pragma unroll
        for (int i = 0; i < 8; i++) {
            const int idx = tid + i * 256;
            const int j = idx & 7;
            if (idx < 1024) {
                const int r = idx >> 3;
                cp16(kvb + r * TROW + j * 16u, K + base + (size_t)(jr + r) * HD + j * 8);
            } else {
                const int r = (idx - 1024) >> 3;
                cp16(kvb + KVTILE_B + r * TROW + j * 16u,
                     V + base + (size_t)(jr + r) * HD + j * 8);
            }
        }
        cp_commit();
    };

    // prologue: stage Q into ring slot 2, load fragments to registers
    {
        const uint32_t qstage = kv_u32 + 2u * KVBUF;
        #pragma unroll
        for (int i = 0; i < 4; i++) {
            const int idx = tid + i * 256;
            const int r = idx >> 3, j = idx & 7;
            cp16(qstage + r * TROW + j * 16u, Q + base + (size_t)(q0 + r) * HD + j * 8);
        }
        cp_commit();
        cp_wait<0>();
        __syncthreads();
    }
    uint32_t qf[4][4];
    {
        const uint32_t qstage = kv_u32 + 2u * KVBUF;
        #pragma unroll
        for (int kb = 0; kb < 4; kb++)
            ldsm4(qf[kb], qstage + q_loff + kb * 32u);
    }
    __syncthreads();

    issue_kv(0);
    if (ktiles > 1) issue_kv(1);
    else cp_commit();

    float m1 = -1e30f, m2 = -1e30f, l1 = 0.f, l2 = 0.f;
    float o[8][4] = {};
    const int grow_base = q0 + rbase;
    const int grow1 = grow_base + g, grow2 = grow1 + 8;

    for (int jt = 0; jt < ktiles; jt++) {
        cp_wait<1>();
        __syncthreads();

        if (jt + 2 < ktiles) issue_kv(jt + 2);
        else cp_commit();

        const uint32_t kt32 = kv_u32 + (uint32_t)(jt % 3) * KVBUF;
        const uint32_t vt32 = kt32 + KVTILE_B;

        #pragma unroll
        for (int sub = 0; sub < 2; sub++) {
            const int j0 = jt * 128 + sub * 64;
            if (j0 > grow_base + 15) break;    // warp-uniform causal skip
            const uint32_t kb32 = kt32 + (uint32_t)(sub * 64) * TROW;
            const uint32_t vb32 = vt32 + (uint32_t)(sub * 64) * TROW;

            float s[8][4] = {};
            #pragma unroll
            for (int kb = 0; kb < 4; kb++) {
                #pragma unroll
                for (int nb = 0; nb < 4; nb++) {
                    uint32_t bf[4];
                    ldsm4(bf, kb32 + b_loff + (uint32_t)(nb * 16) * TROW + kb * 32u);
                    mma_bf16(s[nb * 2],     qf[kb][0], qf[kb][1], qf[kb][2], qf[kb][3],
                             bf[0], bf[1]);
                    mma_bf16(s[nb * 2 + 1], qf[kb][0], qf[kb][1], qf[kb][2], qf[kb][3],
                             bf[2], bf[3]);
                }
            }

            const bool diag = (j0 + 63 > grow_base);
            float rm1 = -1e30f, rm2 = -1e30f;
            #pragma unroll
            for (int nt = 0; nt < 8; nt++) {
                if (diag) {
                    const int c0 = j0 + nt * 8 + 2 * tg;
                    if (c0     > grow1) s[nt][0] = -1e30f;
                    if (c0 + 1 > grow1) s[nt][1] = -1e30f;
                    if (c0     > grow2) s[nt][2] = -1e30f;
                    if (c0 + 1 > grow2) s[nt][3] = -1e30f;
                }
                rm1 = fmaxf(rm1, fmaxf(s[nt][0], s[nt][1]));
                rm2 = fmaxf(rm2, fmaxf(s[nt][2], s[nt][3]));
            }
            rm1 = fmaxf(rm1, __shfl_xor_sync(0xffffffffu, rm1, 1));
            rm1 = fmaxf(rm1, __shfl_xor_sync(0xffffffffu, rm1, 2));
            rm2 = fmaxf(rm2, __shfl_xor_sync(0xffffffffu, rm2, 1));
            rm2 = fmaxf(rm2, __shfl_xor_sync(0xffffffffu, rm2, 2));

            const float mn1 = fmaxf(m1, rm1), mn2 = fmaxf(m2, rm2);
            const float sc1 = ex2f(m1 - mn1), sc2 = ex2f(m2 - mn2);
            m1 = mn1; m2 = mn2;

            float sum1 = 0.f, sum2 = 0.f;
            #pragma unroll
            for (int nt = 0; nt < 8; nt++) {
                s[nt][0] = ex2f(s[nt][0] - mn1);
                s[nt][1] = ex2f(s[nt][1] - mn1);
                s[nt][2] = ex2f(s[nt][2] - mn2);
                s[nt][3] = ex2f(s[nt][3] - mn2);
                sum1 += s[nt][0] + s[nt][1];
                sum2 += s[nt][2] + s[nt][3];
            }
            sum1 += __shfl_xor_sync(0xffffffffu, sum1, 1);
            sum1 += __shfl_xor_sync(0xffffffffu, sum1, 2);
            sum2 += __shfl_xor_sync(0xffffffffu, sum2, 1);
            sum2 += __shfl_xor_sync(0xffffffffu, sum2, 2);
            l1 = l1 * sc1 + sum1;
            l2 = l2 * sc2 + sum2;

            #pragma unroll
            for (int nt = 0; nt < 8; nt++) {
                o[nt][0] *= sc1; o[nt][1] *= sc1;
                o[nt][2] *= sc2; o[nt][3] *= sc2;
            }

            #pragma unroll
            for (int kb = 0; kb < 4; kb++) {
                uint32_t pa[4];
                pa[0] = packbf(s[2 * kb][0],     s[2 * kb][1]);
                pa[1] = packbf(s[2 * kb][2],     s[2 * kb][3]);
                pa[2] = packbf(s[2 * kb + 1][0], s[2 * kb + 1][1]);
                pa[3] = packbf(s[2 * kb + 1][2], s[2 * kb + 1][3]);
                #pragma unroll
                for (int nb = 0; nb < 4; nb++) {
                    uint32_t bf[4];
                    ldsm4t(bf, vb32 + v_loff + (uint32_t)(kb * 16) * TROW + nb * 32u);
                    mma_bf16(o[nb * 2],     pa[0], pa[1], pa[2], pa[3], bf[0], bf[1]);
                    mma_bf16(o[nb * 2 + 1], pa[0], pa[1], pa[2], pa[3], bf[2], bf[3]);
                }
            }
        }
    }

    const float inv1 = 1.0f / l1;
    const float inv2 = 1.0f / l2;
    #pragma unroll
    for (int nt = 0; nt < 8; nt++) {
        const int cb = nt * 8 + 2 * tg;
        *reinterpret_cast<uint32_t*>(O + base + (size_t)grow1 * HD + cb) =
            packbf(o[nt][0] * inv1, o[nt][1] * inv1);
        *reinterpret_cast<uint32_t*>(O + base + (size_t)grow2 * HD + cb) =
            packbf(o[nt][2] * inv2, o[nt][3] * inv2);
    }
}

// ---------------- launch ----------------------------------------------------
extern "C" void kernel_launch(void* const* d_in, const int* in_sizes, int n_in,
                              void* d_out, int out_size) {
    const float* x     = (const float*)d_in[0];
    const float* gamma = (const float*)d_in[1];
    const float* beta  = (const float*)d_in[2];
    const float* Wq    = (const float*)d_in[3];
    const float* bq    = (const float*)d_in[4];
    const float* Wk    = (const float*)d_in[5];
    const float* bk    = (const float*)d_in[6];
    const float* Wv    = (const float*)d_in[7];
    const float* bv    = (const float*)d_in[8];
    const float* Wo    = (const float*)d_in[9];
    const float* bo    = (const float*)d_in[10];
    float* out = (float*)d_out;

    __nv_bfloat16 *xn, *qp, *kp, *vp, *ao, *wb;
    cudaGetSymbolAddress((void**)&xn, g_xn);
    cudaGetSymbolAddress((void**)&qp, g_q);
    cudaGetSymbolAddress((void**)&kp, g_k);
    cudaGetSymbolAddress((void**)&vp, g_v);
    cudaGetSymbolAddress((void**)&ao, g_ao);
    cudaGetSymbolAddress((void**)&wb, g_wb);

    prep_kernel<<<Mrows + 4096, 256>>>(x, gamma, beta, xn, Wq, Wk, Wv, Wo, wb);

    cudaFuncSetAttribute(qkv_gemm_kernel, cudaFuncAttributeMaxDynamicSharedMemorySize,
                         GEMM_SMEM_BYTES);
    cudaFuncSetAttribute(o_gemm_kernel, cudaFuncAttributeMaxDynamicSharedMemorySize,
                         GEMM_SMEM_BYTES);

    qkv_gemm_kernel<<<dim3(24, Mrows / 128), 256, GEMM_SMEM_BYTES>>>(
        xn, wb, bq, bk, bv, qp, kp, vp);

    cudaFuncSetAttribute(attn_bf16_kernel, cudaFuncAttributeMaxDynamicSharedMemorySize,
                         ATTN_SMEM_BYTES);
    attn_bf16_kernel<<<dim3(Sdim / 128, Hdim, Bdim), 256, ATTN_SMEM_BYTES>>>(qp, kp, vp, ao);

    o_gemm_kernel<<<dim3(8, Mrows / 128), 256, GEMM_SMEM_BYTES>>>(ao, wb, bo, x, out);
}